// round 3
// baseline (speedup 1.0000x reference)
#include <cuda_runtime.h>
#include <math.h>

#define NTOK   19600
#define NSEQ   19601
#define PADR   111
#define NP     19712
#define HID    512
#define IND    1024
#define QKV3   192
#define HEADS  8
#define DH     8
#define INNER  64
#define LM     256
#define LSEG   77

// ------------------------- scratch (device globals) ------------------------
__device__ float g_h   [NSEQ * HID];
__device__ float g_hb  [NSEQ * HID];
__device__ float g_xpad[NP * HID];
__device__ float g_qkv [NP * QKV3];
__device__ float g_attnout[NSEQ * INNER];
__device__ float g_ql  [HEADS * LM * DH];
__device__ float g_kl  [HEADS * LM * DH];
__device__ float g_a2  [HEADS * LM * LM];
__device__ float g_z0  [HEADS * LM * LM];
__device__ float g_z1  [HEADS * LM * LM];
__device__ float g_az  [HEADS * LM * LM];
__device__ float g_t1m [HEADS * LM * LM];
__device__ float g_t2m [HEADS * LM * LM];
__device__ float g_av  [HEADS * LM * DH];
__device__ float g_W   [HEADS * LM * DH];
__device__ unsigned int g_scale_bits;
__device__ float g_wcomb[49 * HID];
__device__ float g_bcomb[HID];

// ------------------------------ helpers ------------------------------------
static __device__ __forceinline__ float blockSum128(float v) {
    __shared__ float sh[4];
    #pragma unroll
    for (int o = 16; o; o >>= 1) v += __shfl_xor_sync(0xffffffffu, v, o);
    __syncthreads();
    if ((threadIdx.x & 31) == 0) sh[threadIdx.x >> 5] = v;
    __syncthreads();
    return sh[0] + sh[1] + sh[2] + sh[3];
}

// ------------------------------ generic SGEMM -------------------------------
// C = A(MxK)@B(KxN). 128x128 tile, BK=8, 256 thr, 8x8 microtile.
// EPI: 0 none | 1 bias+GELU | 2 qkv q-scale | 3 C += acc + bias(residual)
template <int EPI>
__global__ void __launch_bounds__(256) sgemm_kernel(
    const float* __restrict__ A, const float* __restrict__ B,
    float* __restrict__ C, const float* __restrict__ X,
    int M, int N, int K, int lda, int ldb, int ldc)
{
    __shared__ float As[8][128];
    __shared__ float Bs[8][128];
    int row0 = blockIdx.x * 128, col0 = blockIdx.y * 128;
    int tid = threadIdx.x;
    int tx = tid & 15, ty = tid >> 4;
    int ar = tid >> 1, ac = (tid & 1) * 4;
    int br = tid >> 5, bc = (tid & 31) * 4;

    float acc[8][8];
    #pragma unroll
    for (int i = 0; i < 8; i++)
        #pragma unroll
        for (int j = 0; j < 8; j++) acc[i][j] = 0.f;

    for (int k0 = 0; k0 < K; k0 += 8) {
        float4 a4 = make_float4(0.f,0.f,0.f,0.f);
        if (row0 + ar < M)
            a4 = *(const float4*)(A + (long)(row0 + ar) * lda + k0 + ac);
        As[ac+0][ar]=a4.x; As[ac+1][ar]=a4.y; As[ac+2][ar]=a4.z; As[ac+3][ar]=a4.w;

        float4 b4 = make_float4(0.f,0.f,0.f,0.f);
        if (col0 + bc < N)
            b4 = *(const float4*)(B + (long)(k0 + br) * ldb + col0 + bc);
        *(float4*)&Bs[br][bc] = b4;
        __syncthreads();

        #pragma unroll
        for (int kk = 0; kk < 8; kk++) {
            float a0[8], b0[8];
            *(float4*)&a0[0] = *(float4*)&As[kk][ty*8];
            *(float4*)&a0[4] = *(float4*)&As[kk][ty*8+4];
            *(float4*)&b0[0] = *(float4*)&Bs[kk][tx*8];
            *(float4*)&b0[4] = *(float4*)&Bs[kk][tx*8+4];
            #pragma unroll
            for (int i = 0; i < 8; i++)
                #pragma unroll
                for (int j = 0; j < 8; j++) acc[i][j] += a0[i] * b0[j];
        }
        __syncthreads();
    }

    #pragma unroll
    for (int i = 0; i < 8; i++) {
        int r = row0 + ty*8 + i;
        if (r >= M) continue;
        #pragma unroll
        for (int j = 0; j < 8; j++) {
            int c = col0 + tx*8 + j;
            if (c >= N) continue;
            float v = acc[i][j];
            long idx = (long)r * ldc + c;
            if (EPI == 0) {
                C[idx] = v;
            } else if (EPI == 1) {
                v += X[c];
                C[idx] = 0.5f * v * (1.f + erff(v * 0.70710678118654752f));
            } else if (EPI == 2) {
                C[idx] = v * (c < 64 ? 0.35355339059327373f : 1.f);
            } else {
                C[idx] += v + X[c];
            }
        }
    }
}

// -------------------- batched 256x256x256 GEMM (pinv) -----------------------
// C = c0 * (A@B) + c1 * X   (per-head batch, all 256x256 row-major)
__global__ void __launch_bounds__(256) sgemm64_kernel(
    const float* __restrict__ A, const float* __restrict__ B,
    float* __restrict__ C, const float* __restrict__ X,
    float c0, float c1)
{
    long off = (long)blockIdx.z * (LM*LM);
    A += off; B += off; C += off;
    const float* Xp = X ? X + off : (const float*)0;
    __shared__ float As[16][64];
    __shared__ float Bs[16][64];
    int row0 = blockIdx.x * 64, col0 = blockIdx.y * 64;
    int tid = threadIdx.x;
    int tx = tid & 15, ty = tid >> 4;
    int ar = tid >> 2, ac = (tid & 3) * 4;
    int br = tid >> 4, bc = (tid & 15) * 4;

    float acc[4][4];
    #pragma unroll
    for (int i=0;i<4;i++)
        #pragma unroll
        for (int j=0;j<4;j++) acc[i][j]=0.f;

    for (int k0 = 0; k0 < LM; k0 += 16) {
        float4 a4 = *(const float4*)(A + (row0+ar)*LM + k0+ac);
        As[ac+0][ar]=a4.x; As[ac+1][ar]=a4.y; As[ac+2][ar]=a4.z; As[ac+3][ar]=a4.w;
        float4 b4 = *(const float4*)(B + (k0+br)*LM + col0+bc);
        *(float4*)&Bs[br][bc] = b4;
        __syncthreads();
        #pragma unroll
        for (int kk=0; kk<16; kk++) {
            float a0[4], b0[4];
            *(float4*)&a0[0] = *(float4*)&As[kk][ty*4];
            *(float4*)&b0[0] = *(float4*)&Bs[kk][tx*4];
            #pragma unroll
            for (int i=0;i<4;i++)
                #pragma unroll
                for (int j=0;j<4;j++) acc[i][j] += a0[i]*b0[j];
        }
        __syncthreads();
    }
    #pragma unroll
    for (int i=0;i<4;i++) {
        int r = row0 + ty*4 + i;
        #pragma unroll
        for (int j=0;j<4;j++) {
            int c = col0 + tx*4 + j;
            long idx = (long)r * LM + c;
            float v = c0 * acc[i][j];
            if (c1 != 0.f) v += c1 * Xp[idx];
            C[idx] = v;
        }
    }
}

// ------------------------------ layernorm -----------------------------------
__global__ void ln_pad_kernel(const float* __restrict__ in, float* __restrict__ out,
                              const float* __restrict__ g, const float* __restrict__ b)
{
    int p = blockIdx.x;
    int tid = threadIdx.x;   // 128
    float* orow = out + (long)p * HID;
    if (p < PADR) {
        *(float4*)(orow + tid*4) = make_float4(0.f,0.f,0.f,0.f);
        return;
    }
    const float* x = in + (long)(p - PADR) * HID;
    float4 v = *(const float4*)(x + tid*4);
    float s = blockSum128(v.x+v.y+v.z+v.w);
    float mu = s * (1.f/512.f);
    float d0=v.x-mu, d1=v.y-mu, d2=v.z-mu, d3=v.w-mu;
    float sq = blockSum128(d0*d0+d1*d1+d2*d2+d3*d3);
    float rstd = rsqrtf(sq*(1.f/512.f) + 1e-5f);
    int c = tid*4;
    orow[c+0]=d0*rstd*g[c+0]+b[c+0]; orow[c+1]=d1*rstd*g[c+1]+b[c+1];
    orow[c+2]=d2*rstd*g[c+2]+b[c+2]; orow[c+3]=d3*rstd*g[c+3]+b[c+3];
}

__global__ void final_ln_kernel(const float* __restrict__ in,
                                const float* __restrict__ g, const float* __restrict__ b,
                                float* __restrict__ out)
{
    int tid = threadIdx.x;   // 128
    float4 v = *(const float4*)(in + tid*4);
    float s = blockSum128(v.x+v.y+v.z+v.w);
    float mu = s * (1.f/512.f);
    float d0=v.x-mu, d1=v.y-mu, d2=v.z-mu, d3=v.w-mu;
    float sq = blockSum128(d0*d0+d1*d1+d2*d2+d3*d3);
    float rstd = rsqrtf(sq*(1.f/512.f) + 1e-5f);
    int c = tid*4;
    out[c+0]=d0*rstd*g[c+0]+b[c+0]; out[c+1]=d1*rstd*g[c+1]+b[c+1];
    out[c+2]=d2*rstd*g[c+2]+b[c+2]; out[c+3]=d3*rstd*g[c+3]+b[c+3];
}

// ------------------------------ landmarks -----------------------------------
__global__ void landmark_kernel()
{
    int i = blockIdx.x;       // landmark
    int c = threadIdx.x;      // 128: 0..63 q, 64..127 k
    const float* base = g_qkv + (long)i * LSEG * QKV3 + c;
    float s = 0.f;
    #pragma unroll 7
    for (int t = 0; t < LSEG; t++) s += base[(long)t * QKV3];
    s *= (1.f/77.f);
    if (c < 64) g_ql[((c>>3)*LM + i)*DH + (c&7)] = s;
    else { int c2 = c-64; g_kl[((c2>>3)*LM + i)*DH + (c2&7)] = s; }
}

// --------------------------- attn2 + softmax --------------------------------
__global__ void attn2_kernel()
{
    int i = blockIdx.x, h = blockIdx.y;
    int j = threadIdx.x;      // 256
    __shared__ float red[256];
    const float* qi = g_ql + (h*LM + i)*DH;
    const float* kj = g_kl + (h*LM + j)*DH;
    float dot = 0.f;
    #pragma unroll
    for (int d = 0; d < DH; d++) dot += qi[d]*kj[d];
    red[j] = dot; __syncthreads();
    for (int s = 128; s > 0; s >>= 1) { if (j < s) red[j] = fmaxf(red[j], red[j+s]); __syncthreads(); }
    float m = red[0]; __syncthreads();
    float p = expf(dot - m);
    red[j] = p; __syncthreads();
    for (int s = 128; s > 0; s >>= 1) { if (j < s) red[j] += red[j+s]; __syncthreads(); }
    g_a2[(h*LM + i)*LM + j] = p / red[0];
}

__global__ void zero_scale_kernel() { g_scale_bits = 0u; }

__global__ void colmax_kernel()
{
    int h = blockIdx.x, j = threadIdx.x;   // 256
    __shared__ float red[256];
    const float* col = g_a2 + h*(LM*LM) + j;
    float s = 0.f;
    for (int i = 0; i < LM; i++) s += col[i*LM];
    red[j] = s; __syncthreads();
    for (int k = 128; k > 0; k >>= 1) { if (j < k) red[j] = fmaxf(red[j], red[j+k]); __syncthreads(); }
    if (j == 0) atomicMax(&g_scale_bits, __float_as_uint(red[0]));
}

__global__ void zinit_kernel()
{
    int i = blockIdx.x, h = blockIdx.y, j = threadIdx.x;
    float scale = __uint_as_float(g_scale_bits);   // rowmax == 1 exactly
    g_z0[h*(LM*LM) + i*LM + j] = g_a2[h*(LM*LM) + j*LM + i] / scale;
}

// --------------------------- attn3 @ v (flash) ------------------------------
__global__ void __launch_bounds__(256) attn3_kernel()
{
    int h = blockIdx.y;
    int tid = threadIdx.x;
    int lmi = tid >> 3, sub = tid & 7;
    int L0 = blockIdx.x * 32 + lmi;
    __shared__ float kt[256][9];
    __shared__ float vt[256][9];

    float q[8];
    #pragma unroll
    for (int d = 0; d < 8; d++) q[d] = g_ql[(h*LM + L0)*DH + d];

    float m = -1e30f;
    for (int t0 = 0; t0 < NP; t0 += 256) {
        const float* kr = g_qkv + (long)(t0 + tid) * QKV3 + 64 + h*8;
        #pragma unroll
        for (int d = 0; d < 8; d++) kt[tid][d] = kr[d];
        __syncthreads();
        for (int j = sub; j < 256; j += 8) {
            float dot = 0.f;
            #pragma unroll
            for (int d = 0; d < 8; d++) dot += q[d]*kt[j][d];
            m = fmaxf(m, dot);
        }
        __syncthreads();
    }
    #pragma unroll
    for (int o = 4; o; o >>= 1) m = fmaxf(m, __shfl_xor_sync(0xffffffffu, m, o));

    float s = 0.f, acc[8];
    #pragma unroll
    for (int d = 0; d < 8; d++) acc[d] = 0.f;
    for (int t0 = 0; t0 < NP; t0 += 256) {
        const float* kr = g_qkv + (long)(t0 + tid) * QKV3 + 64 + h*8;
        #pragma unroll
        for (int d = 0; d < 8; d++) { kt[tid][d] = kr[d]; vt[tid][d] = kr[64+d]; }
        __syncthreads();
        for (int j = sub; j < 256; j += 8) {
            float dot = 0.f;
            #pragma unroll
            for (int d = 0; d < 8; d++) dot += q[d]*kt[j][d];
            float p = expf(dot - m);
            s += p;
            #pragma unroll
            for (int d = 0; d < 8; d++) acc[d] += p * vt[j][d];
        }
        __syncthreads();
    }
    #pragma unroll
    for (int o = 4; o; o >>= 1) {
        s += __shfl_xor_sync(0xffffffffu, s, o);
        #pragma unroll
        for (int d = 0; d < 8; d++) acc[d] += __shfl_xor_sync(0xffffffffu, acc[d], o);
    }
    if (sub == 0) {
        float inv = 1.f / s;
        #pragma unroll
        for (int d = 0; d < 8; d++) g_av[(h*LM + L0)*DH + d] = acc[d]*inv;
    }
}

// --------------------------- W = pinv(a2) @ av ------------------------------
__global__ void wmat_kernel()
{
    int h = blockIdx.x, r = threadIdx.x;   // 256
    __shared__ float avs[256][8];
    #pragma unroll
    for (int d = 0; d < 8; d++) avs[r][d] = g_av[(h*LM + r)*DH + d];
    __syncthreads();
    const float* zr = g_z0 + h*(LM*LM) + r*LM;
    float acc[8];
    #pragma unroll
    for (int d = 0; d < 8; d++) acc[d] = 0.f;
    for (int k = 0; k < LM; k++) {
        float zv = zr[k];
        #pragma unroll
        for (int d = 0; d < 8; d++) acc[d] += zv * avs[k][d];
    }
    #pragma unroll
    for (int d = 0; d < 8; d++) g_W[(h*LM + r)*DH + d] = acc[d];
}

// ----------------------- attn1 @ W + dwconv(v) ------------------------------
__global__ void __launch_bounds__(256) attn1_kernel(const float* __restrict__ resw)
{
    int h = blockIdx.y;
    int tid = threadIdx.x;
    int i = blockIdx.x * 256 + tid;
    __shared__ float kl[256][8];
    __shared__ float Wm[256][8];
    __shared__ float cw[33];
    {
        const float* ks = g_kl + (h*LM + tid)*DH;
        const float* ws = g_W  + (h*LM + tid)*DH;
        *(float4*)&kl[tid][0] = *(const float4*)(ks);
        *(float4*)&kl[tid][4] = *(const float4*)(ks+4);
        *(float4*)&Wm[tid][0] = *(const float4*)(ws);
        *(float4*)&Wm[tid][4] = *(const float4*)(ws+4);
        if (tid < 33) cw[tid] = resw[h*33 + tid];
    }
    __syncthreads();
    if (i >= NSEQ) return;
    int t = PADR + i;
    float q[8];
    {
        const float* qr = g_qkv + (long)t * QKV3 + h*8;
        #pragma unroll
        for (int d = 0; d < 8; d++) q[d] = qr[d];
    }
    float m = -1e30f;
    for (int j = 0; j < 256; j++) {
        float4 k0 = *(float4*)&kl[j][0];
        float4 k1 = *(float4*)&kl[j][4];
        float dot = q[0]*k0.x + q[1]*k0.y + q[2]*k0.z + q[3]*k0.w
                  + q[4]*k1.x + q[5]*k1.y + q[6]*k1.z + q[7]*k1.w;
        m = fmaxf(m, dot);
    }
    float s = 0.f, acc[8];
    #pragma unroll
    for (int d = 0; d < 8; d++) acc[d] = 0.f;
    for (int j = 0; j < 256; j++) {
        float4 k0 = *(float4*)&kl[j][0];
        float4 k1 = *(float4*)&kl[j][4];
        float dot = q[0]*k0.x + q[1]*k0.y + q[2]*k0.z + q[3]*k0.w
                  + q[4]*k1.x + q[5]*k1.y + q[6]*k1.z + q[7]*k1.w;
        float p = expf(dot - m);
        s += p;
        float4 w0 = *(float4*)&Wm[j][0];
        float4 w1 = *(float4*)&Wm[j][4];
        acc[0]+=p*w0.x; acc[1]+=p*w0.y; acc[2]+=p*w0.z; acc[3]+=p*w0.w;
        acc[4]+=p*w1.x; acc[5]+=p*w1.y; acc[6]+=p*w1.z; acc[7]+=p*w1.w;
    }
    float inv = 1.f / s;
    float o[8];
    #pragma unroll
    for (int d = 0; d < 8; d++) o[d] = acc[d]*inv;
    #pragma unroll 4
    for (int k = 0; k < 33; k++) {
        int r = t + k - 16;     // r >= 95 always; upper guard needed
        if (r < NP) {
            const float* vr = g_qkv + (long)r * QKV3 + 128 + h*8;
            float4 v0 = *(const float4*)(vr);
            float4 v1 = *(const float4*)(vr+4);
            float c = cw[k];
            o[0]+=c*v0.x; o[1]+=c*v0.y; o[2]+=c*v0.z; o[3]+=c*v0.w;
            o[4]+=c*v1.x; o[5]+=c*v1.y; o[6]+=c*v1.z; o[7]+=c*v1.w;
        }
    }
    float* outp = g_attnout + (long)i * INNER + h*8;
    *(float4*)(outp)   = make_float4(o[0],o[1],o[2],o[3]);
    *(float4*)(outp+4) = make_float4(o[4],o[5],o[6],o[7]);
}

// ------------------------------ PPEG ----------------------------------------
__global__ void ppeg_prep(const float* __restrict__ w7, const float* __restrict__ b7,
                          const float* __restrict__ w5, const float* __restrict__ b5,
                          const float* __restrict__ w3, const float* __restrict__ b3)
{
    int c = blockIdx.x;      // 512
    int k = threadIdx.x;     // 64
    if (k < 49) {
        int dy = k/7 - 3, dx = k%7 - 3;
        float w = w7[c*49 + k];
        if (dy >= -2 && dy <= 2 && dx >= -2 && dx <= 2) w += w5[c*25 + (dy+2)*5 + (dx+2)];
        if (dy >= -1 && dy <= 1 && dx >= -1 && dx <= 1) w += w3[c*9 + (dy+1)*3 + (dx+1)];
        if (dy == 0 && dx == 0) w += 1.f;
        g_wcomb[k*HID + c] = w;
    }
    if (k == 0) g_bcomb[c] = b7[c] + b5[c] + b3[c];
}

__global__ void __launch_bounds__(256) ppeg_kernel()
{
    int cg = blockIdx.z;
    int px0 = blockIdx.x*8, py0 = blockIdx.y*8;
    int tid = threadIdx.x;
    int cl = tid & 31, pidx = tid >> 5;
    __shared__ float insh[14][14][32];
    __shared__ float wsh[49][32];
    __shared__ float bsh[32];
    for (int idx = tid; idx < 14*14*32; idx += 256) {
        int ch = idx & 31; int pos = idx >> 5;
        int iy = pos/14, ix = pos%14;
        int gy = py0 + iy - 3, gx = px0 + ix - 3;
        float v = 0.f;
        if (gy >= 0 && gy < 140 && gx >= 0 && gx < 140)
            v = g_h[(long)(1 + gy*140 + gx)*HID + cg*32 + ch];
        insh[iy][ix][ch] = v;
    }
    for (int idx = tid; idx < 49*32; idx += 256) {
        int ch = idx & 31, k = idx >> 5;
        wsh[k][ch] = g_wcomb[k*HID + cg*32 + ch];
    }
    if (tid < 32) bsh[tid] = g_bcomb[cg*32 + tid];
    __syncthreads();

    int c = cg*32 + cl;
    int gx = px0 + pidx;
    if (gx >= 140) return;
    for (int yy = 0; yy < 8; yy++) {
        int gy = py0 + yy;
        if (gy >= 140) break;
        float acc = bsh[cl];
        #pragma unroll
        for (int dy = 0; dy < 7; dy++)
            #pragma unroll
            for (int dx = 0; dx < 7; dx++)
                acc += wsh[dy*7+dx][cl] * insh[yy+dy][pidx+dx][cl];
        g_hb[(long)(1 + gy*140 + gx)*HID + c] = acc;
    }
}

__global__ void copy_cls(const float* __restrict__ src, float* __restrict__ dst)
{
    int t = threadIdx.x;   // 256
    dst[t] = src[t];
    dst[t+256] = src[t+256];
}

// ------------------------------ host orchestration --------------------------
extern "C" void kernel_launch(void* const* d_in, const int* in_sizes, int n_in,
                              void* d_out, int out_size)
{
    (void)in_sizes; (void)n_in; (void)out_size;
    const float* x       = (const float*)d_in[0];
    const float* fc1_w   = (const float*)d_in[1];
    const float* fc1_b   = (const float*)d_in[2];
    const float* cls_tok = (const float*)d_in[3];
    const float* l_ng[2] = {(const float*)d_in[4],  (const float*)d_in[10]};
    const float* l_nb[2] = {(const float*)d_in[5],  (const float*)d_in[11]};
    const float* l_qw[2] = {(const float*)d_in[6],  (const float*)d_in[12]};
    const float* l_ow[2] = {(const float*)d_in[7],  (const float*)d_in[13]};
    const float* l_ob[2] = {(const float*)d_in[8],  (const float*)d_in[14]};
    const float* l_rw[2] = {(const float*)d_in[9],  (const float*)d_in[15]};
    const float* p7w = (const float*)d_in[16];
    const float* p7b = (const float*)d_in[17];
    const float* p5w = (const float*)d_in[18];
    const float* p5b = (const float*)d_in[19];
    const float* p3w = (const float*)d_in[20];
    const float* p3b = (const float*)d_in[21];
    const float* norm_g = (const float*)d_in[22];
    const float* norm_b = (const float*)d_in[23];

    float *h, *hb, *xpad, *qkv, *attnout, *a2, *z0, *z1, *az, *t1, *t2;
    cudaGetSymbolAddress((void**)&h,  g_h);
    cudaGetSymbolAddress((void**)&hb, g_hb);
    cudaGetSymbolAddress((void**)&xpad, g_xpad);
    cudaGetSymbolAddress((void**)&qkv,  g_qkv);
    cudaGetSymbolAddress((void**)&attnout, g_attnout);
    cudaGetSymbolAddress((void**)&a2, g_a2);
    cudaGetSymbolAddress((void**)&z0, g_z0);
    cudaGetSymbolAddress((void**)&z1, g_z1);
    cudaGetSymbolAddress((void**)&az, g_az);
    cudaGetSymbolAddress((void**)&t1, g_t1m);
    cudaGetSymbolAddress((void**)&t2, g_t2m);

    // fc1 + GELU -> rows 1.. of g_h; cls -> row 0
    sgemm_kernel<1><<<dim3(154,4,1), 256>>>(x, fc1_w, h + HID, fc1_b,
                                            NTOK, HID, IND, IND, HID, HID);
    copy_cls<<<1,256>>>(cls_tok, h);

    for (int layer = 0; layer < 2; layer++) {
        float* hcur = (layer == 0) ? h : hb;

        ln_pad_kernel<<<NP,128>>>(hcur, xpad, l_ng[layer], l_nb[layer]);
        sgemm_kernel<2><<<dim3(154,2,1), 256>>>(xpad, l_qw[layer], qkv, (const float*)0,
                                                NP, QKV3, HID, HID, QKV3, QKV3);
        landmark_kernel<<<LM,128>>>();
        attn2_kernel<<<dim3(LM,HEADS),256>>>();
        zero_scale_kernel<<<1,1>>>();
        colmax_kernel<<<HEADS,256>>>();
        zinit_kernel<<<dim3(LM,HEADS),256>>>();
        attn3_kernel<<<dim3(8,HEADS),256>>>();

        for (int it = 0; it < 6; it++) {
            float* zin  = (it & 1) ? z1 : z0;
            float* zout = (it & 1) ? z0 : z1;
            dim3 g(4,4,HEADS);
            sgemm64_kernel<<<g,256>>>(a2, zin, az, (const float*)0, 1.f, 0.f);
            sgemm64_kernel<<<g,256>>>(az, az, t1, az, -1.f, 7.f);
            sgemm64_kernel<<<g,256>>>(az, t1, t2, az, -1.f, 15.f);
            sgemm64_kernel<<<g,256>>>(zin, t2, zout, zin, -0.25f, 3.25f);
        }
        wmat_kernel<<<HEADS,256>>>();
        attn1_kernel<<<dim3(77,HEADS),256>>>(l_rw[layer]);
        // out projection + bias + residual into hcur
        sgemm_kernel<3><<<dim3(154,4,1), 256>>>(attnout, l_ow[layer], hcur, l_ob[layer],
                                                NSEQ, HID, INNER, INNER, HID, HID);
        if (layer == 0) {
            ppeg_prep<<<HID,64>>>(p7w, p7b, p5w, p5b, p3w, p3b);
            ppeg_kernel<<<dim3(18,18,16),256>>>();
            copy_cls<<<1,256>>>(h, hb);
        }
    }
    final_ln_kernel<<<1,128>>>(hb, norm_g, norm_b, (float*)d_out);
}

// round 5
// speedup vs baseline: 1.0536x; 1.0536x over previous
#include <cuda_runtime.h>
#include <math.h>

#define NTOK   19600
#define NSEQ   19601
#define PADR   111
#define NP     19712
#define HID    512
#define IND    1024
#define QKV3   192
#define HEADS  8
#define DH     8
#define INNER  64
#define LM     256
#define LSEG   77

// ------------------------- scratch (device globals) ------------------------
__device__ float g_h   [NSEQ * HID];
__device__ float g_hb  [NSEQ * HID];
__device__ float g_xpad[NP * HID];
__device__ float g_qkv [NP * QKV3];
__device__ float g_attnout[NSEQ * INNER];
__device__ float g_ql  [HEADS * LM * DH];
__device__ float g_kl  [HEADS * LM * DH];
__device__ float g_a2  [HEADS * LM * LM];
__device__ float g_z0  [HEADS * LM * LM];
__device__ float g_z1  [HEADS * LM * LM];
__device__ float g_az  [HEADS * LM * LM];
__device__ float g_t1m [HEADS * LM * LM];
__device__ float g_t2m [HEADS * LM * LM];
__device__ float g_av  [HEADS * LM * DH];
__device__ float g_W   [HEADS * LM * DH];
__device__ unsigned int g_scale_bits;
__device__ float g_wcomb[49 * HID];
__device__ float g_bcomb[HID];

// ------------------------------ helpers ------------------------------------
static __device__ __forceinline__ float blockSum128(float v) {
    __shared__ float sh[4];
    #pragma unroll
    for (int o = 16; o; o >>= 1) v += __shfl_xor_sync(0xffffffffu, v, o);
    __syncthreads();
    if ((threadIdx.x & 31) == 0) sh[threadIdx.x >> 5] = v;
    __syncthreads();
    return sh[0] + sh[1] + sh[2] + sh[3];
}

// ------------------------------ generic SGEMM -------------------------------
// C = A(MxK)@B(KxN). 128x128 tile, BK=8, 256 thr, 8x8 microtile.
// Double-buffered smem + register prefetch (1 sync/iter).
// EPI: 0 none | 1 bias+GELU | 2 qkv q-scale | 3 C += acc + bias(residual)
template <int EPI>
__global__ void __launch_bounds__(256) sgemm_kernel(
    const float* __restrict__ A, const float* __restrict__ B,
    float* __restrict__ C, const float* __restrict__ X,
    int M, int N, int K, int lda, int ldb, int ldc)
{
    __shared__ float As[2][8][128];
    __shared__ float Bs[2][8][128];
    int row0 = blockIdx.x * 128, col0 = blockIdx.y * 128;
    int tid = threadIdx.x;
    int tx = tid & 15, ty = tid >> 4;
    int ar = tid >> 1, ac = (tid & 1) * 4;
    int br = tid >> 5, bc = (tid & 31) * 4;

    const bool aok = (row0 + ar < M);
    const bool bok = (col0 + bc < N);
    const float* Aptr = A + (long)(row0 + ar) * lda + ac;
    const float* Bptr = B + (long)br * ldb + col0 + bc;

    float acc[8][8];
    #pragma unroll
    for (int i = 0; i < 8; i++)
        #pragma unroll
        for (int j = 0; j < 8; j++) acc[i][j] = 0.f;

    // prologue: load tile 0 into buffer 0
    float4 a4 = make_float4(0.f,0.f,0.f,0.f);
    float4 b4 = make_float4(0.f,0.f,0.f,0.f);
    if (aok) a4 = *(const float4*)(Aptr);
    if (bok) b4 = *(const float4*)(Bptr);
    As[0][ac+0][ar]=a4.x; As[0][ac+1][ar]=a4.y; As[0][ac+2][ar]=a4.z; As[0][ac+3][ar]=a4.w;
    *(float4*)&Bs[0][br][bc] = b4;
    __syncthreads();

    int nk = K >> 3;
    for (int t = 0; t < nk; t++) {
        int buf = t & 1;
        float4 na = make_float4(0.f,0.f,0.f,0.f);
        float4 nb = make_float4(0.f,0.f,0.f,0.f);
        if (t + 1 < nk) {
            int k0 = (t + 1) << 3;
            if (aok) na = *(const float4*)(Aptr + k0);
            if (bok) nb = *(const float4*)(Bptr + (long)k0 * ldb);
        }
        #pragma unroll
        for (int kk = 0; kk < 8; kk++) {
            float a0[8], b0[8];
            *(float4*)&a0[0] = *(float4*)&As[buf][kk][ty*8];
            *(float4*)&a0[4] = *(float4*)&As[buf][kk][ty*8+4];
            *(float4*)&b0[0] = *(float4*)&Bs[buf][kk][tx*8];
            *(float4*)&b0[4] = *(float4*)&Bs[buf][kk][tx*8+4];
            #pragma unroll
            for (int i = 0; i < 8; i++)
                #pragma unroll
                for (int j = 0; j < 8; j++) acc[i][j] += a0[i] * b0[j];
        }
        if (t + 1 < nk) {
            int nb_ = buf ^ 1;
            As[nb_][ac+0][ar]=na.x; As[nb_][ac+1][ar]=na.y;
            As[nb_][ac+2][ar]=na.z; As[nb_][ac+3][ar]=na.w;
            *(float4*)&Bs[nb_][br][bc] = nb;
            __syncthreads();
        }
    }

    #pragma unroll
    for (int i = 0; i < 8; i++) {
        int r = row0 + ty*8 + i;
        if (r >= M) continue;
        #pragma unroll
        for (int j = 0; j < 8; j++) {
            int c = col0 + tx*8 + j;
            if (c >= N) continue;
            float v = acc[i][j];
            long idx = (long)r * ldc + c;
            if (EPI == 0) {
                C[idx] = v;
            } else if (EPI == 1) {
                v += X[c];
                C[idx] = 0.5f * v * (1.f + erff(v * 0.70710678118654752f));
            } else if (EPI == 2) {
                C[idx] = v * (c < 64 ? 0.35355339059327373f : 1.f);
            } else {
                C[idx] += v + X[c];
            }
        }
    }
}

// -------------------- batched 256x256x256 GEMM (pinv) -----------------------
// C = c0 * (A@B) + c1 * X   (per-head batch, all 256x256 row-major)
// Double-buffered.
__global__ void __launch_bounds__(256) sgemm64_kernel(
    const float* __restrict__ A, const float* __restrict__ B,
    float* __restrict__ C, const float* __restrict__ X,
    float c0, float c1)
{
    long off = (long)blockIdx.z * (LM*LM);
    A += off; B += off; C += off;
    const float* Xp = X ? X + off : (const float*)0;
    __shared__ float As[2][16][64];
    __shared__ float Bs[2][16][64];
    int row0 = blockIdx.x * 64, col0 = blockIdx.y * 64;
    int tid = threadIdx.x;
    int tx = tid & 15, ty = tid >> 4;
    int ar = tid >> 2, ac = (tid & 3) * 4;
    int br = tid >> 4, bc = (tid & 15) * 4;

    const float* Aptr = A + (row0 + ar) * LM + ac;
    const float* Bptr = B + br * LM + col0 + bc;

    float acc[4][4];
    #pragma unroll
    for (int i=0;i<4;i++)
        #pragma unroll
        for (int j=0;j<4;j++) acc[i][j]=0.f;

    float4 a4 = *(const float4*)(Aptr);
    float4 b4 = *(const float4*)(Bptr);
    As[0][ac+0][ar]=a4.x; As[0][ac+1][ar]=a4.y; As[0][ac+2][ar]=a4.z; As[0][ac+3][ar]=a4.w;
    *(float4*)&Bs[0][br][bc] = b4;
    __syncthreads();

    const int nk = LM / 16;   // 16
    for (int t = 0; t < nk; t++) {
        int buf = t & 1;
        float4 na, nb;
        if (t + 1 < nk) {
            int k0 = (t + 1) * 16;
            na = *(const float4*)(Aptr + k0);
            nb = *(const float4*)(Bptr + k0 * LM);
        }
        #pragma unroll
        for (int kk=0; kk<16; kk++) {
            float a0[4], b0[4];
            *(float4*)&a0[0] = *(float4*)&As[buf][kk][ty*4];
            *(float4*)&b0[0] = *(float4*)&Bs[buf][kk][tx*4];
            #pragma unroll
            for (int i=0;i<4;i++)
                #pragma unroll
                for (int j=0;j<4;j++) acc[i][j] += a0[i]*b0[j];
        }
        if (t + 1 < nk) {
            int nb_ = buf ^ 1;
            As[nb_][ac+0][ar]=na.x; As[nb_][ac+1][ar]=na.y;
            As[nb_][ac+2][ar]=na.z; As[nb_][ac+3][ar]=na.w;
            *(float4*)&Bs[nb_][br][bc] = nb;
            __syncthreads();
        }
    }
    #pragma unroll
    for (int i=0;i<4;i++) {
        int r = row0 + ty*4 + i;
        #pragma unroll
        for (int j=0;j<4;j++) {
            int c = col0 + tx*4 + j;
            long idx = (long)r * LM + c;
            float v = c0 * acc[i][j];
            if (c1 != 0.f) v += c1 * Xp[idx];
            C[idx] = v;
        }
    }
}

// ------------------------------ layernorm -----------------------------------
__global__ void ln_pad_kernel(const float* __restrict__ in, float* __restrict__ out,
                              const float* __restrict__ g, const float* __restrict__ b)
{
    int p = blockIdx.x;
    int tid = threadIdx.x;   // 128
    float* orow = out + (long)p * HID;
    if (p < PADR) {
        *(float4*)(orow + tid*4) = make_float4(0.f,0.f,0.f,0.f);
        return;
    }
    const float* x = in + (long)(p - PADR) * HID;
    float4 v = *(const float4*)(x + tid*4);
    float s = blockSum128(v.x+v.y+v.z+v.w);
    float mu = s * (1.f/512.f);
    float d0=v.x-mu, d1=v.y-mu, d2=v.z-mu, d3=v.w-mu;
    float sq = blockSum128(d0*d0+d1*d1+d2*d2+d3*d3);
    float rstd = rsqrtf(sq*(1.f/512.f) + 1e-5f);
    int c = tid*4;
    orow[c+0]=d0*rstd*g[c+0]+b[c+0]; orow[c+1]=d1*rstd*g[c+1]+b[c+1];
    orow[c+2]=d2*rstd*g[c+2]+b[c+2]; orow[c+3]=d3*rstd*g[c+3]+b[c+3];
}

__global__ void final_ln_kernel(const float* __restrict__ in,
                                const float* __restrict__ g, const float* __restrict__ b,
                                float* __restrict__ out)
{
    int tid = threadIdx.x;   // 128
    float4 v = *(const float4*)(in + tid*4);
    float s = blockSum128(v.x+v.y+v.z+v.w);
    float mu = s * (1.f/512.f);
    float d0=v.x-mu, d1=v.y-mu, d2=v.z-mu, d3=v.w-mu;
    float sq = blockSum128(d0*d0+d1*d1+d2*d2+d3*d3);
    float rstd = rsqrtf(sq*(1.f/512.f) + 1e-5f);
    int c = tid*4;
    out[c+0]=d0*rstd*g[c+0]+b[c+0]; out[c+1]=d1*rstd*g[c+1]+b[c+1];
    out[c+2]=d2*rstd*g[c+2]+b[c+2]; out[c+3]=d3*rstd*g[c+3]+b[c+3];
}

// ------------------------------ landmarks -----------------------------------
__global__ void landmark_kernel()
{
    int i = blockIdx.x;       // landmark
    int c = threadIdx.x;      // 128: 0..63 q, 64..127 k
    const float* base = g_qkv + (long)i * LSEG * QKV3 + c;
    float s = 0.f;
    #pragma unroll 7
    for (int t = 0; t < LSEG; t++) s += base[(long)t * QKV3];
    s *= (1.f/77.f);
    if (c < 64) g_ql[((c>>3)*LM + i)*DH + (c&7)] = s;
    else { int c2 = c-64; g_kl[((c2>>3)*LM + i)*DH + (c2&7)] = s; }
}

// --------------------------- attn2 + softmax --------------------------------
__global__ void attn2_kernel()
{
    int i = blockIdx.x, h = blockIdx.y;
    int j = threadIdx.x;      // 256
    __shared__ float red[256];
    const float* qi = g_ql + (h*LM + i)*DH;
    const float* kj = g_kl + (h*LM + j)*DH;
    float dot = 0.f;
    #pragma unroll
    for (int d = 0; d < DH; d++) dot += qi[d]*kj[d];
    red[j] = dot; __syncthreads();
    for (int s = 128; s > 0; s >>= 1) { if (j < s) red[j] = fmaxf(red[j], red[j+s]); __syncthreads(); }
    float m = red[0]; __syncthreads();
    float p = expf(dot - m);
    red[j] = p; __syncthreads();
    for (int s = 128; s > 0; s >>= 1) { if (j < s) red[j] += red[j+s]; __syncthreads(); }
    g_a2[(h*LM + i)*LM + j] = p / red[0];
}

__global__ void zero_scale_kernel() { g_scale_bits = 0u; }

__global__ void colmax_kernel()
{
    int h = blockIdx.x, j = threadIdx.x;   // 256
    __shared__ float red[256];
    const float* col = g_a2 + h*(LM*LM) + j;
    float s = 0.f;
    for (int i = 0; i < LM; i++) s += col[i*LM];
    red[j] = s; __syncthreads();
    for (int k = 128; k > 0; k >>= 1) { if (j < k) red[j] = fmaxf(red[j], red[j+k]); __syncthreads(); }
    if (j == 0) atomicMax(&g_scale_bits, __float_as_uint(red[0]));
}

__global__ void zinit_kernel()
{
    int i = blockIdx.x, h = blockIdx.y, j = threadIdx.x;
    float scale = __uint_as_float(g_scale_bits);   // rowmax == 1 exactly
    g_z0[h*(LM*LM) + i*LM + j] = g_a2[h*(LM*LM) + j*LM + i] / scale;
}

// --------------------------- attn3 @ v (flash) ------------------------------
__global__ void __launch_bounds__(256) attn3_kernel()
{
    int h = blockIdx.y;
    int tid = threadIdx.x;
    int lmi = tid >> 3, sub = tid & 7;
    int L0 = blockIdx.x * 32 + lmi;
    __shared__ float kt[256][9];
    __shared__ float vt[256][9];

    float q[8];
    #pragma unroll
    for (int d = 0; d < 8; d++) q[d] = g_ql[(h*LM + L0)*DH + d];

    float m = -1e30f;
    for (int t0 = 0; t0 < NP; t0 += 256) {
        const float* kr = g_qkv + (long)(t0 + tid) * QKV3 + 64 + h*8;
        #pragma unroll
        for (int d = 0; d < 8; d++) kt[tid][d] = kr[d];
        __syncthreads();
        for (int j = sub; j < 256; j += 8) {
            float dot = 0.f;
            #pragma unroll
            for (int d = 0; d < 8; d++) dot += q[d]*kt[j][d];
            m = fmaxf(m, dot);
        }
        __syncthreads();
    }
    #pragma unroll
    for (int o = 4; o; o >>= 1) m = fmaxf(m, __shfl_xor_sync(0xffffffffu, m, o));

    float s = 0.f, acc[8];
    #pragma unroll
    for (int d = 0; d < 8; d++) acc[d] = 0.f;
    for (int t0 = 0; t0 < NP; t0 += 256) {
        const float* kr = g_qkv + (long)(t0 + tid) * QKV3 + 64 + h*8;
        #pragma unroll
        for (int d = 0; d < 8; d++) { kt[tid][d] = kr[d]; vt[tid][d] = kr[64+d]; }
        __syncthreads();
        for (int j = sub; j < 256; j += 8) {
            float dot = 0.f;
            #pragma unroll
            for (int d = 0; d < 8; d++) dot += q[d]*kt[j][d];
            float p = expf(dot - m);
            s += p;
            #pragma unroll
            for (int d = 0; d < 8; d++) acc[d] += p * vt[j][d];
        }
        __syncthreads();
    }
    #pragma unroll
    for (int o = 4; o; o >>= 1) {
        s += __shfl_xor_sync(0xffffffffu, s, o);
        #pragma unroll
        for (int d = 0; d < 8; d++) acc[d] += __shfl_xor_sync(0xffffffffu, acc[d], o);
    }
    if (sub == 0) {
        float inv = 1.f / s;
        #pragma unroll
        for (int d = 0; d < 8; d++) g_av[(h*LM + L0)*DH + d] = acc[d]*inv;
    }
}

// --------------------------- W = pinv(a2) @ av ------------------------------
__global__ void wmat_kernel()
{
    int h = blockIdx.x, r = threadIdx.x;   // 256
    __shared__ float avs[256][8];
    #pragma unroll
    for (int d = 0; d < 8; d++) avs[r][d] = g_av[(h*LM + r)*DH + d];
    __syncthreads();
    const float* zr = g_z0 + h*(LM*LM) + r*LM;
    float acc[8];
    #pragma unroll
    for (int d = 0; d < 8; d++) acc[d] = 0.f;
    for (int k = 0; k < LM; k++) {
        float zv = zr[k];
        #pragma unroll
        for (int d = 0; d < 8; d++) acc[d] += zv * avs[k][d];
    }
    #pragma unroll
    for (int d = 0; d < 8; d++) g_W[(h*LM + r)*DH + d] = acc[d];
}

// ----------------------- attn1 @ W + dwconv(v) ------------------------------
__global__ void __launch_bounds__(256) attn1_kernel(const float* __restrict__ resw)
{
    int h = blockIdx.y;
    int tid = threadIdx.x;
    int i = blockIdx.x * 256 + tid;
    __shared__ float kl[256][8];
    __shared__ float Wm[256][8];
    __shared__ float cw[33];
    {
        const float* ks = g_kl + (h*LM + tid)*DH;
        const float* ws = g_W  + (h*LM + tid)*DH;
        *(float4*)&kl[tid][0] = *(const float4*)(ks);
        *(float4*)&kl[tid][4] = *(const float4*)(ks+4);
        *(float4*)&Wm[tid][0] = *(const float4*)(ws);
        *(float4*)&Wm[tid][4] = *(const float4*)(ws+4);
        if (tid < 33) cw[tid] = resw[h*33 + tid];
    }
    __syncthreads();
    if (i >= NSEQ) return;
    int t = PADR + i;
    float q[8];
    {
        const float* qr = g_qkv + (long)t * QKV3 + h*8;
        #pragma unroll
        for (int d = 0; d < 8; d++) q[d] = qr[d];
    }
    float m = -1e30f;
    for (int j = 0; j < 256; j++) {
        float4 k0 = *(float4*)&kl[j][0];
        float4 k1 = *(float4*)&kl[j][4];
        float dot = q[0]*k0.x + q[1]*k0.y + q[2]*k0.z + q[3]*k0.w
                  + q[4]*k1.x + q[5]*k1.y + q[6]*k1.z + q[7]*k1.w;
        m = fmaxf(m, dot);
    }
    float s = 0.f, acc[8];
    #pragma unroll
    for (int d = 0; d < 8; d++) acc[d] = 0.f;
    for (int j = 0; j < 256; j++) {
        float4 k0 = *(float4*)&kl[j][0];
        float4 k1 = *(float4*)&kl[j][4];
        float dot = q[0]*k0.x + q[1]*k0.y + q[2]*k0.z + q[3]*k0.w
                  + q[4]*k1.x + q[5]*k1.y + q[6]*k1.z + q[7]*k1.w;
        float p = expf(dot - m);
        s += p;
        float4 w0 = *(float4*)&Wm[j][0];
        float4 w1 = *(float4*)&Wm[j][4];
        acc[0]+=p*w0.x; acc[1]+=p*w0.y; acc[2]+=p*w0.z; acc[3]+=p*w0.w;
        acc[4]+=p*w1.x; acc[5]+=p*w1.y; acc[6]+=p*w1.z; acc[7]+=p*w1.w;
    }
    float inv = 1.f / s;
    float o[8];
    #pragma unroll
    for (int d = 0; d < 8; d++) o[d] = acc[d]*inv;
    #pragma unroll 4
    for (int k = 0; k < 33; k++) {
        int r = t + k - 16;     // r >= 95 always; upper guard needed
        if (r < NP) {
            const float* vr = g_qkv + (long)r * QKV3 + 128 + h*8;
            float4 v0 = *(const float4*)(vr);
            float4 v1 = *(const float4*)(vr+4);
            float c = cw[k];
            o[0]+=c*v0.x; o[1]+=c*v0.y; o[2]+=c*v0.z; o[3]+=c*v0.w;
            o[4]+=c*v1.x; o[5]+=c*v1.y; o[6]+=c*v1.z; o[7]+=c*v1.w;
        }
    }
    float* outp = g_attnout + (long)i * INNER + h*8;
    *(float4*)(outp)   = make_float4(o[0],o[1],o[2],o[3]);
    *(float4*)(outp+4) = make_float4(o[4],o[5],o[6],o[7]);
}

// ------------------------------ PPEG ----------------------------------------
__global__ void ppeg_prep(const float* __restrict__ w7, const float* __restrict__ b7,
                          const float* __restrict__ w5, const float* __restrict__ b5,
                          const float* __restrict__ w3, const float* __restrict__ b3)
{
    int c = blockIdx.x;      // 512
    int k = threadIdx.x;     // 64
    if (k < 49) {
        int dy = k/7 - 3, dx = k%7 - 3;
        float w = w7[c*49 + k];
        if (dy >= -2 && dy <= 2 && dx >= -2 && dx <= 2) w += w5[c*25 + (dy+2)*5 + (dx+2)];
        if (dy >= -1 && dy <= 1 && dx >= -1 && dx <= 1) w += w3[c*9 + (dy+1)*3 + (dx+1)];
        if (dy == 0 && dx == 0) w += 1.f;
        g_wcomb[k*HID + c] = w;
    }
    if (k == 0) g_bcomb[c] = b7[c] + b5[c] + b3[c];
}

__global__ void __launch_bounds__(256) ppeg_kernel()
{
    int cg = blockIdx.z;
    int px0 = blockIdx.x*8, py0 = blockIdx.y*8;
    int tid = threadIdx.x;
    int cl = tid & 31, pidx = tid >> 5;
    __shared__ float insh[14][14][32];
    __shared__ float wsh[49][32];
    __shared__ float bsh[32];
    for (int idx = tid; idx < 14*14*32; idx += 256) {
        int ch = idx & 31; int pos = idx >> 5;
        int iy = pos/14, ix = pos%14;
        int gy = py0 + iy - 3, gx = px0 + ix - 3;
        float v = 0.f;
        if (gy >= 0 && gy < 140 && gx >= 0 && gx < 140)
            v = g_h[(long)(1 + gy*140 + gx)*HID + cg*32 + ch];
        insh[iy][ix][ch] = v;
    }
    for (int idx = tid; idx < 49*32; idx += 256) {
        int ch = idx & 31, k = idx >> 5;
        wsh[k][ch] = g_wcomb[k*HID + cg*32 + ch];
    }
    if (tid < 32) bsh[tid] = g_bcomb[cg*32 + tid];
    __syncthreads();

    int c = cg*32 + cl;
    int gx = px0 + pidx;
    if (gx >= 140) return;
    for (int yy = 0; yy < 8; yy++) {
        int gy = py0 + yy;
        if (gy >= 140) break;
        float acc = bsh[cl];
        #pragma unroll
        for (int dy = 0; dy < 7; dy++)
            #pragma unroll
            for (int dx = 0; dx < 7; dx++)
                acc += wsh[dy*7+dx][cl] * insh[yy+dy][pidx+dx][cl];
        g_hb[(long)(1 + gy*140 + gx)*HID + c] = acc;
    }
}

__global__ void copy_cls(const float* __restrict__ src, float* __restrict__ dst)
{
    int t = threadIdx.x;   // 256
    dst[t] = src[t];
    dst[t+256] = src[t+256];
}

// ------------------------------ host orchestration --------------------------
extern "C" void kernel_launch(void* const* d_in, const int* in_sizes, int n_in,
                              void* d_out, int out_size)
{
    (void)in_sizes; (void)n_in; (void)out_size;
    const float* x       = (const float*)d_in[0];
    const float* fc1_w   = (const float*)d_in[1];
    const float* fc1_b   = (const float*)d_in[2];
    const float* cls_tok = (const float*)d_in[3];
    const float* l_ng[2] = {(const float*)d_in[4],  (const float*)d_in[10]};
    const float* l_nb[2] = {(const float*)d_in[5],  (const float*)d_in[11]};
    const float* l_qw[2] = {(const float*)d_in[6],  (const float*)d_in[12]};
    const float* l_ow[2] = {(const float*)d_in[7],  (const float*)d_in[13]};
    const float* l_ob[2] = {(const float*)d_in[8],  (const float*)d_in[14]};
    const float* l_rw[2] = {(const float*)d_in[9],  (const float*)d_in[15]};
    const float* p7w = (const float*)d_in[16];
    const float* p7b = (const float*)d_in[17];
    const float* p5w = (const float*)d_in[18];
    const float* p5b = (const float*)d_in[19];
    const float* p3w = (const float*)d_in[20];
    const float* p3b = (const float*)d_in[21];
    const float* norm_g = (const float*)d_in[22];
    const float* norm_b = (const float*)d_in[23];

    float *h, *hb, *xpad, *qkv, *attnout, *a2, *z0, *z1, *az, *t1, *t2;
    cudaGetSymbolAddress((void**)&h,  g_h);
    cudaGetSymbolAddress((void**)&hb, g_hb);
    cudaGetSymbolAddress((void**)&xpad, g_xpad);
    cudaGetSymbolAddress((void**)&qkv,  g_qkv);
    cudaGetSymbolAddress((void**)&attnout, g_attnout);
    cudaGetSymbolAddress((void**)&a2, g_a2);
    cudaGetSymbolAddress((void**)&z0, g_z0);
    cudaGetSymbolAddress((void**)&z1, g_z1);
    cudaGetSymbolAddress((void**)&az, g_az);
    cudaGetSymbolAddress((void**)&t1, g_t1m);
    cudaGetSymbolAddress((void**)&t2, g_t2m);

    // fc1 + GELU -> rows 1.. of g_h; cls -> row 0
    sgemm_kernel<1><<<dim3(154,4,1), 256>>>(x, fc1_w, h + HID, fc1_b,
                                            NTOK, HID, IND, IND, HID, HID);
    copy_cls<<<1,256>>>(cls_tok, h);

    for (int layer = 0; layer < 2; layer++) {
        float* hcur = (layer == 0) ? h : hb;

        ln_pad_kernel<<<NP,128>>>(hcur, xpad, l_ng[layer], l_nb[layer]);
        sgemm_kernel<2><<<dim3(154,2,1), 256>>>(xpad, l_qw[layer], qkv, (const float*)0,
                                                NP, QKV3, HID, HID, QKV3, QKV3);
        landmark_kernel<<<LM,128>>>();
        attn2_kernel<<<dim3(LM,HEADS),256>>>();
        zero_scale_kernel<<<1,1>>>();
        colmax_kernel<<<HEADS,256>>>();
        zinit_kernel<<<dim3(LM,HEADS),256>>>();
        attn3_kernel<<<dim3(8,HEADS),256>>>();

        for (int it = 0; it < 6; it++) {
            float* zin  = (it & 1) ? z1 : z0;
            float* zout = (it & 1) ? z0 : z1;
            dim3 g(4,4,HEADS);
            sgemm64_kernel<<<g,256>>>(a2, zin, az, (const float*)0, 1.f, 0.f);
            sgemm64_kernel<<<g,256>>>(az, az, t1, az, -1.f, 7.f);
            sgemm64_kernel<<<g,256>>>(az, t1, t2, az, -1.f, 15.f);
            sgemm64_kernel<<<g,256>>>(zin, t2, zout, zin, -0.25f, 3.25f);
        }
        wmat_kernel<<<HEADS,256>>>();
        attn1_kernel<<<dim3(77,HEADS),256>>>(l_rw[layer]);
        // out projection + bias + residual into hcur
        sgemm_kernel<3><<<dim3(154,4,1), 256>>>(attnout, l_ow[layer], hcur, l_ob[layer],
                                                NSEQ, HID, INNER, INNER, HID, HID);
        if (layer == 0) {
            ppeg_prep<<<HID,64>>>(p7w, p7b, p5w, p5b, p3w, p3b);
            ppeg_kernel<<<dim3(18,18,16),256>>>();
            copy_cls<<<1,256>>>(h, hb);
        }
    }
    final_ln_kernel<<<1,128>>>(hb, norm_g, norm_b, (float*)d_out);
}

// round 8
// speedup vs baseline: 1.1821x; 1.1220x over previous
#include <cuda_runtime.h>
#include <math.h>
#include <stdint.h>

#define NTOK   19600
#define NSEQ   19601
#define PADR   111
#define NP     19712
#define HID    512
#define IND    1024
#define QKV3   192
#define HEADS  8
#define DH     8
#define INNER  64
#define LM     256
#define LSEG   77

// ------------------------- scratch (device globals) ------------------------
__device__ float g_h   [NSEQ * HID];
__device__ float g_hb  [NSEQ * HID];
__device__ float g_xpad[NP * HID];
__device__ float g_qkv [NP * QKV3];
__device__ float g_attnout[NSEQ * INNER];
__device__ float g_ql  [HEADS * LM * DH];
__device__ float g_kl  [HEADS * LM * DH];
__device__ float g_a2  [HEADS * LM * LM];
__device__ float g_z0  [HEADS * LM * LM];
__device__ float g_z1  [HEADS * LM * LM];
__device__ float g_az  [HEADS * LM * LM];
__device__ float g_t1m [HEADS * LM * LM];
__device__ float g_t2m [HEADS * LM * LM];
__device__ float g_av  [HEADS * LM * DH];
__device__ float g_W   [HEADS * LM * DH];
__device__ unsigned int g_scale_bits;
__device__ float g_wcomb[49 * HID];
__device__ float g_bcomb[HID];
__device__ float g_wT  [HID * IND];      // fc1_w transposed [N=512][K=1024], tf32-rounded

static __device__ __forceinline__ float tf32r(float x) {
    float r; asm("cvt.rna.tf32.f32 %0, %1;" : "=f"(r) : "f"(x)); return r;
}

// one m16n8k8 tf32 mma.sync
static __device__ __forceinline__ void mma_tf32(
    float& c0, float& c1, float& c2, float& c3,
    float a0, float a1, float a2, float a3, float b0, float b1)
{
    asm volatile(
        "mma.sync.aligned.m16n8k8.row.col.f32.tf32.tf32.f32 "
        "{%0,%1,%2,%3}, {%4,%5,%6,%7}, {%8,%9}, {%0,%1,%2,%3};"
        : "+f"(c0), "+f"(c1), "+f"(c2), "+f"(c3)
        : "r"(__float_as_uint(a0)), "r"(__float_as_uint(a1)),
          "r"(__float_as_uint(a2)), "r"(__float_as_uint(a3)),
          "r"(__float_as_uint(b0)), "r"(__float_as_uint(b1)));
}

// ------------------------- fc1_w transpose (+tf32 round) --------------------
__global__ void transpose_w_kernel(const float* __restrict__ w, float* __restrict__ wt)
{
    __shared__ float t[32][33];
    int k0 = blockIdx.x * 32, n0 = blockIdx.y * 32;
    int tx = threadIdx.x, ty = threadIdx.y;        // 32 x 8
    #pragma unroll
    for (int i = ty; i < 32; i += 8)
        t[i][tx] = w[(long)(k0 + i) * HID + n0 + tx];
    __syncthreads();
    #pragma unroll
    for (int i = ty; i < 32; i += 8)
        wt[(long)(n0 + i) * IND + k0 + tx] = tf32r(t[tx][i]);
}

// ----------------- fc1 via mma.sync tf32 (128x128 tile, BK=16) --------------
// D[m][n] = sum_k X[row0+m][k] * WT[col0+n][k]; epilogue bias + exact GELU.
// SMEM k-permuted per 16-chunk: kperm = (k%4)*4 + k/4, so fragment loads are LDS128.
__global__ void __launch_bounds__(256) fc1_mma_kernel(
    const float* __restrict__ X, const float* __restrict__ WT,
    const float* __restrict__ bias, float* __restrict__ Hout)
{
    __shared__ float As[2][128][20];
    __shared__ float Bs[2][128][20];

    int tid  = threadIdx.x;
    int lane = tid & 31, wid = tid >> 5;
    int g = lane >> 2, tig = lane & 3;
    int wm = wid & 3, wn = wid >> 2;          // 4 M-slabs x 2 N-slabs
    int row0 = blockIdx.x * 128, col0 = blockIdx.y * 128;

    int lr = tid >> 1;                        // loader row (0..127)
    int ks = (tid & 1);                       // k half (0/1)
    const bool aok = (row0 + lr) < NTOK;
    const float* ap = X  + (long)(row0 + lr) * IND + ks * 8;
    const float* bp = WT + (long)(col0 + lr) * IND + ks * 8;

    float acc[2][8][4];
    #pragma unroll
    for (int mt = 0; mt < 2; mt++)
        #pragma unroll
        for (int nt = 0; nt < 8; nt++)
            #pragma unroll
            for (int q = 0; q < 4; q++) acc[mt][nt][q] = 0.f;

    // prologue prefetch (tile 0)
    float4 la0 = make_float4(0.f,0.f,0.f,0.f), la1 = la0;
    if (aok) { la0 = *(const float4*)(ap); la1 = *(const float4*)(ap + 4); }
    float4 lb0 = *(const float4*)(bp);
    float4 lb1 = *(const float4*)(bp + 4);

    const int NIT = IND / 16;                 // 64
    for (int it = 0; it < NIT; it++) {
        int buf = it & 1;
        {   // STS with k-permutation; A rounded to tf32
            int c0i = ks * 2, c1i = ks * 2 + 1;
            float* Ar = &As[buf][lr][0];
            float* Br = &Bs[buf][lr][0];
            Ar[0*4 + c0i] = tf32r(la0.x); Ar[1*4 + c0i] = tf32r(la0.y);
            Ar[2*4 + c0i] = tf32r(la0.z); Ar[3*4 + c0i] = tf32r(la0.w);
            Ar[0*4 + c1i] = tf32r(la1.x); Ar[1*4 + c1i] = tf32r(la1.y);
            Ar[2*4 + c1i] = tf32r(la1.z); Ar[3*4 + c1i] = tf32r(la1.w);
            Br[0*4 + c0i] = lb0.x; Br[1*4 + c0i] = lb0.y;
            Br[2*4 + c0i] = lb0.z; Br[3*4 + c0i] = lb0.w;
            Br[0*4 + c1i] = lb1.x; Br[1*4 + c1i] = lb1.y;
            Br[2*4 + c1i] = lb1.z; Br[3*4 + c1i] = lb1.w;
        }
        __syncthreads();
        if (it + 1 < NIT) {
            int k0 = (it + 1) * 16;
            if (aok) { la0 = *(const float4*)(ap + k0); la1 = *(const float4*)(ap + k0 + 4); }
            lb0 = *(const float4*)(bp + k0);
            lb1 = *(const float4*)(bp + k0 + 4);
        }
        // fragments
        float4 va[2], vb[2];
        #pragma unroll
        for (int mt = 0; mt < 2; mt++) {
            int rr = wm * 32 + mt * 16 + g;
            va[mt] = *(float4*)&As[buf][rr][tig * 4];
            vb[mt] = *(float4*)&As[buf][rr + 8][tig * 4];
        }
        #pragma unroll
        for (int nt = 0; nt < 8; nt++) {
            int nn = wn * 64 + nt * 8 + g;
            float4 wv = *(float4*)&Bs[buf][nn][tig * 4];
            #pragma unroll
            for (int mt = 0; mt < 2; mt++) {
                // k-step 0: k = tig, tig+4
                mma_tf32(acc[mt][nt][0], acc[mt][nt][1], acc[mt][nt][2], acc[mt][nt][3],
                         va[mt].x, vb[mt].x, va[mt].y, vb[mt].y, wv.x, wv.y);
                // k-step 1: k = 8+tig, 12+tig
                mma_tf32(acc[mt][nt][0], acc[mt][nt][1], acc[mt][nt][2], acc[mt][nt][3],
                         va[mt].z, vb[mt].z, va[mt].w, vb[mt].w, wv.z, wv.w);
            }
        }
        __syncthreads();
    }

    // epilogue: bias + exact GELU, direct to global (rows shifted by 1 for cls)
    #pragma unroll
    for (int mt = 0; mt < 2; mt++) {
        int r1 = row0 + wm * 32 + mt * 16 + g;
        int r2 = r1 + 8;
        #pragma unroll
        for (int nt = 0; nt < 8; nt++) {
            int cc = col0 + wn * 64 + nt * 8 + tig * 2;
            float bia0 = bias[cc], bia1 = bias[cc + 1];
            if (r1 < NTOK) {
                float v0 = acc[mt][nt][0] + bia0;
                float v1 = acc[mt][nt][1] + bia1;
                float* d = Hout + (long)(1 + r1) * HID + cc;
                d[0] = 0.5f * v0 * (1.f + erff(v0 * 0.70710678118654752f));
                d[1] = 0.5f * v1 * (1.f + erff(v1 * 0.70710678118654752f));
            }
            if (r2 < NTOK) {
                float v2 = acc[mt][nt][2] + bia0;
                float v3 = acc[mt][nt][3] + bia1;
                float* d = Hout + (long)(1 + r2) * HID + cc;
                d[0] = 0.5f * v2 * (1.f + erff(v2 * 0.70710678118654752f));
                d[1] = 0.5f * v3 * (1.f + erff(v3 * 0.70710678118654752f));
            }
        }
    }
}

// ------------------------------ helpers ------------------------------------
static __device__ __forceinline__ float blockSum128(float v) {
    __shared__ float sh[4];
    #pragma unroll
    for (int o = 16; o; o >>= 1) v += __shfl_xor_sync(0xffffffffu, v, o);
    __syncthreads();
    if ((threadIdx.x & 31) == 0) sh[threadIdx.x >> 5] = v;
    __syncthreads();
    return sh[0] + sh[1] + sh[2] + sh[3];
}

// ------------------------------ generic SGEMM -------------------------------
template <int EPI>
__global__ void __launch_bounds__(256) sgemm_kernel(
    const float* __restrict__ A, const float* __restrict__ B,
    float* __restrict__ C, const float* __restrict__ X,
    int M, int N, int K, int lda, int ldb, int ldc)
{
    __shared__ float As[2][8][128];
    __shared__ float Bs[2][8][128];
    int row0 = blockIdx.x * 128, col0 = blockIdx.y * 128;
    int tid = threadIdx.x;
    int tx = tid & 15, ty = tid >> 4;
    int ar = tid >> 1, ac = (tid & 1) * 4;
    int br = tid >> 5, bc = (tid & 31) * 4;

    const bool aok = (row0 + ar < M);
    const bool bok = (col0 + bc < N);
    const float* Aptr = A + (long)(row0 + ar) * lda + ac;
    const float* Bptr = B + (long)br * ldb + col0 + bc;

    float acc[8][8];
    #pragma unroll
    for (int i = 0; i < 8; i++)
        #pragma unroll
        for (int j = 0; j < 8; j++) acc[i][j] = 0.f;

    float4 a4 = make_float4(0.f,0.f,0.f,0.f);
    float4 b4 = make_float4(0.f,0.f,0.f,0.f);
    if (aok) a4 = *(const float4*)(Aptr);
    if (bok) b4 = *(const float4*)(Bptr);
    As[0][ac+0][ar]=a4.x; As[0][ac+1][ar]=a4.y; As[0][ac+2][ar]=a4.z; As[0][ac+3][ar]=a4.w;
    *(float4*)&Bs[0][br][bc] = b4;
    __syncthreads();

    int nk = K >> 3;
    for (int t = 0; t < nk; t++) {
        int buf = t & 1;
        float4 na = make_float4(0.f,0.f,0.f,0.f);
        float4 nb = make_float4(0.f,0.f,0.f,0.f);
        if (t + 1 < nk) {
            int k0 = (t + 1) << 3;
            if (aok) na = *(const float4*)(Aptr + k0);
            if (bok) nb = *(const float4*)(Bptr + (long)k0 * ldb);
        }
        #pragma unroll
        for (int kk = 0; kk < 8; kk++) {
            float a0[8], b0[8];
            *(float4*)&a0[0] = *(float4*)&As[buf][kk][ty*8];
            *(float4*)&a0[4] = *(float4*)&As[buf][kk][ty*8+4];
            *(float4*)&b0[0] = *(float4*)&Bs[buf][kk][tx*8];
            *(float4*)&b0[4] = *(float4*)&Bs[buf][kk][tx*8+4];
            #pragma unroll
            for (int i = 0; i < 8; i++)
                #pragma unroll
                for (int j = 0; j < 8; j++) acc[i][j] += a0[i] * b0[j];
        }
        if (t + 1 < nk) {
            int nb_ = buf ^ 1;
            As[nb_][ac+0][ar]=na.x; As[nb_][ac+1][ar]=na.y;
            As[nb_][ac+2][ar]=na.z; As[nb_][ac+3][ar]=na.w;
            *(float4*)&Bs[nb_][br][bc] = nb;
            __syncthreads();
        }
    }

    #pragma unroll
    for (int i = 0; i < 8; i++) {
        int r = row0 + ty*8 + i;
        if (r >= M) continue;
        #pragma unroll
        for (int j = 0; j < 8; j++) {
            int c = col0 + tx*8 + j;
            if (c >= N) continue;
            float v = acc[i][j];
            long idx = (long)r * ldc + c;
            if (EPI == 0) {
                C[idx] = v;
            } else if (EPI == 1) {
                v += X[c];
                C[idx] = 0.5f * v * (1.f + erff(v * 0.70710678118654752f));
            } else if (EPI == 2) {
                C[idx] = v * (c < 64 ? 0.35355339059327373f : 1.f);
            } else {
                C[idx] += v + X[c];
            }
        }
    }
}

// -------------------- batched 256x256x256 GEMM (pinv) -----------------------
__global__ void __launch_bounds__(256) sgemm64_kernel(
    const float* __restrict__ A, const float* __restrict__ B,
    float* __restrict__ C, const float* __restrict__ X,
    float c0, float c1)
{
    long off = (long)blockIdx.z * (LM*LM);
    A += off; B += off; C += off;
    const float* Xp = X ? X + off : (const float*)0;
    __shared__ float As[2][16][64];
    __shared__ float Bs[2][16][64];
    int row0 = blockIdx.x * 64, col0 = blockIdx.y * 64;
    int tid = threadIdx.x;
    int tx = tid & 15, ty = tid >> 4;
    int ar = tid >> 2, ac = (tid & 3) * 4;
    int br = tid >> 4, bc = (tid & 15) * 4;

    const float* Aptr = A + (row0 + ar) * LM + ac;
    const float* Bptr = B + br * LM + col0 + bc;

    float acc[4][4];
    #pragma unroll
    for (int i=0;i<4;i++)
        #pragma unroll
        for (int j=0;j<4;j++) acc[i][j]=0.f;

    float4 a4 = *(const float4*)(Aptr);
    float4 b4 = *(const float4*)(Bptr);
    As[0][ac+0][ar]=a4.x; As[0][ac+1][ar]=a4.y; As[0][ac+2][ar]=a4.z; As[0][ac+3][ar]=a4.w;
    *(float4*)&Bs[0][br][bc] = b4;
    __syncthreads();

    const int nk = LM / 16;
    for (int t = 0; t < nk; t++) {
        int buf = t & 1;
        float4 na, nb;
        if (t + 1 < nk) {
            int k0 = (t + 1) * 16;
            na = *(const float4*)(Aptr + k0);
            nb = *(const float4*)(Bptr + k0 * LM);
        }
        #pragma unroll
        for (int kk=0; kk<16; kk++) {
            float a0[4], b0[4];
            *(float4*)&a0[0] = *(float4*)&As[buf][kk][ty*4];
            *(float4*)&b0[0] = *(float4*)&Bs[buf][kk][tx*4];
            #pragma unroll
            for (int i=0;i<4;i++)
                #pragma unroll
                for (int j=0;j<4;j++) acc[i][j] += a0[i]*b0[j];
        }
        if (t + 1 < nk) {
            int nb_ = buf ^ 1;
            As[nb_][ac+0][ar]=na.x; As[nb_][ac+1][ar]=na.y;
            As[nb_][ac+2][ar]=na.z; As[nb_][ac+3][ar]=na.w;
            *(float4*)&Bs[nb_][br][bc] = nb;
            __syncthreads();
        }
    }
    #pragma unroll
    for (int i=0;i<4;i++) {
        int r = row0 + ty*4 + i;
        #pragma unroll
        for (int j=0;j<4;j++) {
            int c = col0 + tx*4 + j;
            long idx = (long)r * LM + c;
            float v = c0 * acc[i][j];
            if (c1 != 0.f) v += c1 * Xp[idx];
            C[idx] = v;
        }
    }
}

// ------------------------------ layernorm -----------------------------------
__global__ void ln_pad_kernel(const float* __restrict__ in, float* __restrict__ out,
                              const float* __restrict__ g, const float* __restrict__ b)
{
    int p = blockIdx.x;
    int tid = threadIdx.x;
    float* orow = out + (long)p * HID;
    if (p < PADR) {
        *(float4*)(orow + tid*4) = make_float4(0.f,0.f,0.f,0.f);
        return;
    }
    const float* x = in + (long)(p - PADR) * HID;
    float4 v = *(const float4*)(x + tid*4);
    float s = blockSum128(v.x+v.y+v.z+v.w);
    float mu = s * (1.f/512.f);
    float d0=v.x-mu, d1=v.y-mu, d2=v.z-mu, d3=v.w-mu;
    float sq = blockSum128(d0*d0+d1*d1+d2*d2+d3*d3);
    float rstd = rsqrtf(sq*(1.f/512.f) + 1e-5f);
    int c = tid*4;
    orow[c+0]=d0*rstd*g[c+0]+b[c+0]; orow[c+1]=d1*rstd*g[c+1]+b[c+1];
    orow[c+2]=d2*rstd*g[c+2]+b[c+2]; orow[c+3]=d3*rstd*g[c+3]+b[c+3];
}

__global__ void final_ln_kernel(const float* __restrict__ in,
                                const float* __restrict__ g, const float* __restrict__ b,
                                float* __restrict__ out)
{
    int tid = threadIdx.x;
    float4 v = *(const float4*)(in + tid*4);
    float s = blockSum128(v.x+v.y+v.z+v.w);
    float mu = s * (1.f/512.f);
    float d0=v.x-mu, d1=v.y-mu, d2=v.z-mu, d3=v.w-mu;
    float sq = blockSum128(d0*d0+d1*d1+d2*d2+d3*d3);
    float rstd = rsqrtf(sq*(1.f/512.f) + 1e-5f);
    int c = tid*4;
    out[c+0]=d0*rstd*g[c+0]+b[c+0]; out[c+1]=d1*rstd*g[c+1]+b[c+1];
    out[c+2]=d2*rstd*g[c+2]+b[c+2]; out[c+3]=d3*rstd*g[c+3]+b[c+3];
}

// ------------------------------ landmarks -----------------------------------
__global__ void landmark_kernel()
{
    int i = blockIdx.x;
    int c = threadIdx.x;
    const float* base = g_qkv + (long)i * LSEG * QKV3 + c;
    float s = 0.f;
    #pragma unroll 7
    for (int t = 0; t < LSEG; t++) s += base[(long)t * QKV3];
    s *= (1.f/77.f);
    if (c < 64) g_ql[((c>>3)*LM + i)*DH + (c&7)] = s;
    else { int c2 = c-64; g_kl[((c2>>3)*LM + i)*DH + (c2&7)] = s; }
}

// --------------------------- attn2 + softmax --------------------------------
__global__ void attn2_kernel()
{
    int i = blockIdx.x, h = blockIdx.y;
    int j = threadIdx.x;
    __shared__ float red[256];
    const float* qi = g_ql + (h*LM + i)*DH;
    const float* kj = g_kl + (h*LM + j)*DH;
    float dot = 0.f;
    #pragma unroll
    for (int d = 0; d < DH; d++) dot += qi[d]*kj[d];
    red[j] = dot; __syncthreads();
    for (int s = 128; s > 0; s >>= 1) { if (j < s) red[j] = fmaxf(red[j], red[j+s]); __syncthreads(); }
    float m = red[0]; __syncthreads();
    float p = expf(dot - m);
    red[j] = p; __syncthreads();
    for (int s = 128; s > 0; s >>= 1) { if (j < s) red[j] += red[j+s]; __syncthreads(); }
    g_a2[(h*LM + i)*LM + j] = p / red[0];
}

__global__ void zero_scale_kernel() { g_scale_bits = 0u; }

__global__ void colmax_kernel()
{
    int h = blockIdx.x, j = threadIdx.x;
    __shared__ float red[256];
    const float* col = g_a2 + h*(LM*LM) + j;
    float s = 0.f;
    for (int i = 0; i < LM; i++) s += col[i*LM];
    red[j] = s; __syncthreads();
    for (int k = 128; k > 0; k >>= 1) { if (j < k) red[j] = fmaxf(red[j], red[j+k]); __syncthreads(); }
    if (j == 0) atomicMax(&g_scale_bits, __float_as_uint(red[0]));
}

__global__ void zinit_kernel()
{
    int i = blockIdx.x, h = blockIdx.y, j = threadIdx.x;
    float scale = __uint_as_float(g_scale_bits);
    g_z0[h*(LM*LM) + i*LM + j] = g_a2[h*(LM*LM) + j*LM + i] / scale;
}

// --------------------------- attn3 @ v (flash) ------------------------------
__global__ void __launch_bounds__(256) attn3_kernel()
{
    int h = blockIdx.y;
    int tid = threadIdx.x;
    int lmi = tid >> 3, sub = tid & 7;
    int L0 = blockIdx.x * 32 + lmi;
    __shared__ float kt[256][9];
    __shared__ float vt[256][9];

    float q[8];
    #pragma unroll
    for (int d = 0; d < 8; d++) q[d] = g_ql[(h*LM + L0)*DH + d];

    float m = -1e30f;
    for (int t0 = 0; t0 < NP; t0 += 256) {
        const float* kr = g_qkv + (long)(t0 + tid) * QKV3 + 64 + h*8;
        #pragma unroll
        for (int d = 0; d < 8; d++) kt[tid][d] = kr[d];
        __syncthreads();
        for (int j = sub; j < 256; j += 8) {
            float dot = 0.f;
            #pragma unroll
            for (int d = 0; d < 8; d++) dot += q[d]*kt[j][d];
            m = fmaxf(m, dot);
        }
        __syncthreads();
    }
    #pragma unroll
    for (int o = 4; o; o >>= 1) m = fmaxf(m, __shfl_xor_sync(0xffffffffu, m, o));

    float s = 0.f, acc[8];
    #pragma unroll
    for (int d = 0; d < 8; d++) acc[d] = 0.f;
    for (int t0 = 0; t0 < NP; t0 += 256) {
        const float* kr = g_qkv + (long)(t0 + tid) * QKV3 + 64 + h*8;
        #pragma unroll
        for (int d = 0; d < 8; d++) { kt[tid][d] = kr[d]; vt[tid][d] = kr[64+d]; }
        __syncthreads();
        for (int j = sub; j < 256; j += 8) {
            float dot = 0.f;
            #pragma unroll
            for (int d = 0; d < 8; d++) dot += q[d]*kt[j][d];
            float p = expf(dot - m);
            s += p;
            #pragma unroll
            for (int d = 0; d < 8; d++) acc[d] += p * vt[j][d];
        }
        __syncthreads();
    }
    #pragma unroll
    for (int o = 4; o; o >>= 1) {
        s += __shfl_xor_sync(0xffffffffu, s, o);
        #pragma unroll
        for (int d = 0; d < 8; d++) acc[d] += __shfl_xor_sync(0xffffffffu, acc[d], o);
    }
    if (sub == 0) {
        float inv = 1.f / s;
        #pragma unroll
        for (int d = 0; d < 8; d++) g_av[(h*LM + L0)*DH + d] = acc[d]*inv;
    }
}

// --------------------------- W = pinv(a2) @ av ------------------------------
__global__ void wmat_kernel()
{
    int h = blockIdx.x, r = threadIdx.x;
    __shared__ float avs[256][8];
    #pragma unroll
    for (int d = 0; d < 8; d++) avs[r][d] = g_av[(h*LM + r)*DH + d];
    __syncthreads();
    const float* zr = g_z0 + h*(LM*LM) + r*LM;
    float acc[8];
    #pragma unroll
    for (int d = 0; d < 8; d++) acc[d] = 0.f;
    for (int k = 0; k < LM; k++) {
        float zv = zr[k];
        #pragma unroll
        for (int d = 0; d < 8; d++) acc[d] += zv * avs[k][d];
    }
    #pragma unroll
    for (int d = 0; d < 8; d++) g_W[(h*LM + r)*DH + d] = acc[d];
}

// ----------------------- attn1 @ W + dwconv(v) ------------------------------
__global__ void __launch_bounds__(256) attn1_kernel(const float* __restrict__ resw)
{
    int h = blockIdx.y;
    int tid = threadIdx.x;
    int i = blockIdx.x * 256 + tid;
    __shared__ float kl[256][8];
    __shared__ float Wm[256][8];
    __shared__ float cw[33];
    {
        const float* ks = g_kl + (h*LM + tid)*DH;
        const float* ws = g_W  + (h*LM + tid)*DH;
        *(float4*)&kl[tid][0] = *(const float4*)(ks);
        *(float4*)&kl[tid][4] = *(const float4*)(ks+4);
        *(float4*)&Wm[tid][0] = *(const float4*)(ws);
        *(float4*)&Wm[tid][4] = *(const float4*)(ws+4);
        if (tid < 33) cw[tid] = resw[h*33 + tid];
    }
    __syncthreads();
    if (i >= NSEQ) return;
    int t = PADR + i;
    float q[8];
    {
        const float* qr = g_qkv + (long)t * QKV3 + h*8;
        #pragma unroll
        for (int d = 0; d < 8; d++) q[d] = qr[d];
    }
    float m = -1e30f;
    for (int j = 0; j < 256; j++) {
        float4 k0 = *(float4*)&kl[j][0];
        float4 k1 = *(float4*)&kl[j][4];
        float dot = q[0]*k0.x + q[1]*k0.y + q[2]*k0.z + q[3]*k0.w
                  + q[4]*k1.x + q[5]*k1.y + q[6]*k1.z + q[7]*k1.w;
        m = fmaxf(m, dot);
    }
    float s = 0.f, acc[8];
    #pragma unroll
    for (int d = 0; d < 8; d++) acc[d] = 0.f;
    for (int j = 0; j < 256; j++) {
        float4 k0 = *(float4*)&kl[j][0];
        float4 k1 = *(float4*)&kl[j][4];
        float dot = q[0]*k0.x + q[1]*k0.y + q[2]*k0.z + q[3]*k0.w
                  + q[4]*k1.x + q[5]*k1.y + q[6]*k1.z + q[7]*k1.w;
        float p = expf(dot - m);
        s += p;
        float4 w0 = *(float4*)&Wm[j][0];
        float4 w1 = *(float4*)&Wm[j][4];
        acc[0]+=p*w0.x; acc[1]+=p*w0.y; acc[2]+=p*w0.z; acc[3]+=p*w0.w;
        acc[4]+=p*w1.x; acc[5]+=p*w1.y; acc[6]+=p*w1.z; acc[7]+=p*w1.w;
    }
    float inv = 1.f / s;
    float o[8];
    #pragma unroll
    for (int d = 0; d < 8; d++) o[d] = acc[d]*inv;
    #pragma unroll 4
    for (int k = 0; k < 33; k++) {
        int r = t + k - 16;
        if (r < NP) {
            const float* vr = g_qkv + (long)r * QKV3 + 128 + h*8;
            float4 v0 = *(const float4*)(vr);
            float4 v1 = *(const float4*)(vr+4);
            float c = cw[k];
            o[0]+=c*v0.x; o[1]+=c*v0.y; o[2]+=c*v0.z; o[3]+=c*v0.w;
            o[4]+=c*v1.x; o[5]+=c*v1.y; o[6]+=c*v1.z; o[7]+=c*v1.w;
        }
    }
    float* outp = g_attnout + (long)i * INNER + h*8;
    *(float4*)(outp)   = make_float4(o[0],o[1],o[2],o[3]);
    *(float4*)(outp+4) = make_float4(o[4],o[5],o[6],o[7]);
}

// ------------------------------ PPEG ----------------------------------------
__global__ void ppeg_prep(const float* __restrict__ w7, const float* __restrict__ b7,
                          const float* __restrict__ w5, const float* __restrict__ b5,
                          const float* __restrict__ w3, const float* __restrict__ b3)
{
    int c = blockIdx.x;
    int k = threadIdx.x;
    if (k < 49) {
        int dy = k/7 - 3, dx = k%7 - 3;
        float w = w7[c*49 + k];
        if (dy >= -2 && dy <= 2 && dx >= -2 && dx <= 2) w += w5[c*25 + (dy+2)*5 + (dx+2)];
        if (dy >= -1 && dy <= 1 && dx >= -1 && dx <= 1) w += w3[c*9 + (dy+1)*3 + (dx+1)];
        if (dy == 0 && dx == 0) w += 1.f;
        g_wcomb[k*HID + c] = w;
    }
    if (k == 0) g_bcomb[c] = b7[c] + b5[c] + b3[c];
}

__global__ void __launch_bounds__(256) ppeg_kernel()
{
    int cg = blockIdx.z;
    int px0 = blockIdx.x*8, py0 = blockIdx.y*8;
    int tid = threadIdx.x;
    int cl = tid & 31, pidx = tid >> 5;
    __shared__ float insh[14][14][32];
    __shared__ float wsh[49][32];
    __shared__ float bsh[32];
    for (int idx = tid; idx < 14*14*32; idx += 256) {
        int ch = idx & 31; int pos = idx >> 5;
        int iy = pos/14, ix = pos%14;
        int gy = py0 + iy - 3, gx = px0 + ix - 3;
        float v = 0.f;
        if (gy >= 0 && gy < 140 && gx >= 0 && gx < 140)
            v = g_h[(long)(1 + gy*140 + gx)*HID + cg*32 + ch];
        insh[iy][ix][ch] = v;
    }
    for (int idx = tid; idx < 49*32; idx += 256) {
        int ch = idx & 31, k = idx >> 5;
        wsh[k][ch] = g_wcomb[k*HID + cg*32 + ch];
    }
    if (tid < 32) bsh[tid] = g_bcomb[cg*32 + tid];
    __syncthreads();

    int c = cg*32 + cl;
    int gx = px0 + pidx;
    if (gx >= 140) return;
    for (int yy = 0; yy < 8; yy++) {
        int gy = py0 + yy;
        if (gy >= 140) break;
        float acc = bsh[cl];
        #pragma unroll
        for (int dy = 0; dy < 7; dy++)
            #pragma unroll
            for (int dx = 0; dx < 7; dx++)
                acc += wsh[dy*7+dx][cl] * insh[yy+dy][pidx+dx][cl];
        g_hb[(long)(1 + gy*140 + gx)*HID + c] = acc;
    }
}

__global__ void copy_cls(const float* __restrict__ src, float* __restrict__ dst)
{
    int t = threadIdx.x;
    dst[t] = src[t];
    dst[t+256] = src[t+256];
}

// ------------------------------ host orchestration --------------------------
extern "C" void kernel_launch(void* const* d_in, const int* in_sizes, int n_in,
                              void* d_out, int out_size)
{
    (void)in_sizes; (void)n_in; (void)out_size;
    const float* x       = (const float*)d_in[0];
    const float* fc1_w   = (const float*)d_in[1];
    const float* fc1_b   = (const float*)d_in[2];
    const float* cls_tok = (const float*)d_in[3];
    const float* l_ng[2] = {(const float*)d_in[4],  (const float*)d_in[10]};
    const float* l_nb[2] = {(const float*)d_in[5],  (const float*)d_in[11]};
    const float* l_qw[2] = {(const float*)d_in[6],  (const float*)d_in[12]};
    const float* l_ow[2] = {(const float*)d_in[7],  (const float*)d_in[13]};
    const float* l_ob[2] = {(const float*)d_in[8],  (const float*)d_in[14]};
    const float* l_rw[2] = {(const float*)d_in[9],  (const float*)d_in[15]};
    const float* p7w = (const float*)d_in[16];
    const float* p7b = (const float*)d_in[17];
    const float* p5w = (const float*)d_in[18];
    const float* p5b = (const float*)d_in[19];
    const float* p3w = (const float*)d_in[20];
    const float* p3b = (const float*)d_in[21];
    const float* norm_g = (const float*)d_in[22];
    const float* norm_b = (const float*)d_in[23];

    float *h, *hb, *xpad, *qkv, *attnout, *a2, *z0, *z1, *az, *t1, *t2, *wT;
    cudaGetSymbolAddress((void**)&h,  g_h);
    cudaGetSymbolAddress((void**)&hb, g_hb);
    cudaGetSymbolAddress((void**)&xpad, g_xpad);
    cudaGetSymbolAddress((void**)&qkv,  g_qkv);
    cudaGetSymbolAddress((void**)&attnout, g_attnout);
    cudaGetSymbolAddress((void**)&a2, g_a2);
    cudaGetSymbolAddress((void**)&z0, g_z0);
    cudaGetSymbolAddress((void**)&z1, g_z1);
    cudaGetSymbolAddress((void**)&az, g_az);
    cudaGetSymbolAddress((void**)&t1, g_t1m);
    cudaGetSymbolAddress((void**)&t2, g_t2m);
    cudaGetSymbolAddress((void**)&wT, g_wT);

    // fc1 + GELU via mma.sync tf32 -> rows 1.. of g_h; cls -> row 0
    transpose_w_kernel<<<dim3(IND/32, HID/32), dim3(32,8)>>>(fc1_w, wT);
    fc1_mma_kernel<<<dim3(154, 4), 256>>>(x, wT, fc1_b, h);
    copy_cls<<<1,256>>>(cls_tok, h);

    for (int layer = 0; layer < 2; layer++) {
        float* hcur = (layer == 0) ? h : hb;

        ln_pad_kernel<<<NP,128>>>(hcur, xpad, l_ng[layer], l_nb[layer]);
        sgemm_kernel<2><<<dim3(154,2,1), 256>>>(xpad, l_qw[layer], qkv, (const float*)0,
                                                NP, QKV3, HID, HID, QKV3, QKV3);
        landmark_kernel<<<LM,128>>>();
        attn2_kernel<<<dim3(LM,HEADS),256>>>();
        zero_scale_kernel<<<1,1>>>();
        colmax_kernel<<<HEADS,256>>>();
        zinit_kernel<<<dim3(LM,HEADS),256>>>();
        attn3_kernel<<<dim3(8,HEADS),256>>>();

        for (int it = 0; it < 6; it++) {
            float* zin  = (it & 1) ? z1 : z0;
            float* zout = (it & 1) ? z0 : z1;
            dim3 g(4,4,HEADS);
            sgemm64_kernel<<<g,256>>>(a2, zin, az, (const float*)0, 1.f, 0.f);
            sgemm64_kernel<<<g,256>>>(az, az, t1, az, -1.f, 7.f);
            sgemm64_kernel<<<g,256>>>(az, t1, t2, az, -1.f, 15.f);
            sgemm64_kernel<<<g,256>>>(zin, t2, zout, zin, -0.25f, 3.25f);
        }
        wmat_kernel<<<HEADS,256>>>();
        attn1_kernel<<<dim3(77,HEADS),256>>>(l_rw[layer]);
        sgemm_kernel<3><<<dim3(154,4,1), 256>>>(attnout, l_ow[layer], hcur, l_ob[layer],
                                                NSEQ, HID, INNER, INNER, HID, HID);
        if (layer == 0) {
            ppeg_prep<<<HID,64>>>(p7w, p7b, p5w, p5b, p3w, p3b);
            ppeg_kernel<<<dim3(18,18,16),256>>>();
            copy_cls<<<1,256>>>(h, hb);
        }
    }
    final_ln_kernel<<<1,128>>>(hb, norm_g, norm_b, (float*)d_out);
}

// round 11
// speedup vs baseline: 1.2534x; 1.0603x over previous
#include <cuda_runtime.h>
#include <math.h>
#include <stdint.h>

#define NTOK   19600
#define NSEQ   19601
#define PADR   111
#define NP     19712
#define HID    512
#define IND    1024
#define QKV3   192
#define HEADS  8
#define DH     8
#define INNER  64
#define LM     256
#define LSEG   77

// ------------------------- scratch (device globals) ------------------------
__device__ float g_h   [NSEQ * HID];
__device__ float g_hb  [NSEQ * HID];
__device__ float g_xpad[NP * HID];
__device__ float g_qkv [NP * QKV3];
__device__ float g_attnout[NSEQ * INNER];
__device__ float g_ql  [HEADS * LM * DH];
__device__ float g_kl  [HEADS * LM * DH];
__device__ float g_a2  [HEADS * LM * LM];
__device__ float g_z0  [HEADS * LM * LM];
__device__ float g_z1  [HEADS * LM * LM];
__device__ float g_az  [HEADS * LM * LM];
__device__ float g_t1m [HEADS * LM * LM];
__device__ float g_t2m [HEADS * LM * LM];
__device__ float g_av  [HEADS * LM * DH];
__device__ float g_W   [HEADS * LM * DH];
__device__ unsigned int g_scale_bits;
__device__ float g_wcomb[49 * HID];
__device__ float g_bcomb[HID];
__device__ float g_wT  [HID * IND];      // fc1_w^T  [512][1024] tf32
__device__ float g_qkvT[256 * HID];      // qkv_w^T  [256(pad)][512] tf32
__device__ float g_owT [HID * INNER];    // out_w^T  [512][64] tf32

static __device__ __forceinline__ float tf32r(float x) {
    float r; asm("cvt.rna.tf32.f32 %0, %1;" : "=f"(r) : "f"(x)); return r;
}

// one m16n8k8 tf32 mma.sync
static __device__ __forceinline__ void mma_tf32(
    float& c0, float& c1, float& c2, float& c3,
    float a0, float a1, float a2, float a3, float b0, float b1)
{
    asm volatile(
        "mma.sync.aligned.m16n8k8.row.col.f32.tf32.tf32.f32 "
        "{%0,%1,%2,%3}, {%4,%5,%6,%7}, {%8,%9}, {%0,%1,%2,%3};"
        : "+f"(c0), "+f"(c1), "+f"(c2), "+f"(c3)
        : "r"(__float_as_uint(a0)), "r"(__float_as_uint(a1)),
          "r"(__float_as_uint(a2)), "r"(__float_as_uint(a3)),
          "r"(__float_as_uint(b0)), "r"(__float_as_uint(b1)));
}

// ------------------- generic transpose + pad + tf32 round -------------------
// w [K][N] -> wt [Npad][K] (Npad = gridDim.y*32), zero-filled for n >= N.
__global__ void transpose_pad_kernel(const float* __restrict__ w, float* __restrict__ wt,
                                     int K, int N)
{
    __shared__ float t[32][33];
    int k0 = blockIdx.x * 32, n0 = blockIdx.y * 32;
    int tx = threadIdx.x, ty = threadIdx.y;        // 32 x 8
    #pragma unroll
    for (int i = ty; i < 32; i += 8)
        t[i][tx] = (n0 + tx < N) ? w[(long)(k0 + i) * N + n0 + tx] : 0.f;
    __syncthreads();
    #pragma unroll
    for (int i = ty; i < 32; i += 8)
        wt[(long)(n0 + i) * K + k0 + tx] = tf32r(t[tx][i]);
}

// -------------- generic tf32 mma GEMM: 128x128 tile, BK=16, 256 thr ---------
// C[m][n] = sum_k A[m][k] * BT[n][k]   (BT pre-transposed + tf32-rounded)
// EPI: 1 bias+GELU | 2 qkv q-scale | 3 C += acc + X (residual)
template <int EPI>
__global__ void __launch_bounds__(256) gemm_mma_kernel(
    const float* __restrict__ A, const float* __restrict__ BT,
    float* __restrict__ C, const float* __restrict__ X,
    int M, int Nreal, int K, int lda, int ldc)
{
    __shared__ float As[2][128][20];
    __shared__ float Bs[2][128][20];

    int tid  = threadIdx.x;
    int lane = tid & 31, wid = tid >> 5;
    int g = lane >> 2, tig = lane & 3;
    int wm = wid & 3, wn = wid >> 2;
    int row0 = blockIdx.x * 128, col0 = blockIdx.y * 128;

    int lr = tid >> 1;
    int ks = tid & 1;
    const bool aok = (row0 + lr) < M;
    const float* ap = A  + (long)(row0 + lr) * lda + ks * 8;
    const float* bp = BT + (long)(col0 + lr) * K   + ks * 8;

    float acc[2][8][4];
    #pragma unroll
    for (int mt = 0; mt < 2; mt++)
        #pragma unroll
        for (int nt = 0; nt < 8; nt++)
            #pragma unroll
            for (int q = 0; q < 4; q++) acc[mt][nt][q] = 0.f;

    float4 la0 = make_float4(0.f,0.f,0.f,0.f), la1 = la0;
    if (aok) { la0 = *(const float4*)(ap); la1 = *(const float4*)(ap + 4); }
    float4 lb0 = *(const float4*)(bp);
    float4 lb1 = *(const float4*)(bp + 4);

    const int NIT = K / 16;
    for (int it = 0; it < NIT; it++) {
        int buf = it & 1;
        {
            int c0i = ks * 2, c1i = ks * 2 + 1;
            float* Ar = &As[buf][lr][0];
            float* Br = &Bs[buf][lr][0];
            Ar[0*4 + c0i] = tf32r(la0.x); Ar[1*4 + c0i] = tf32r(la0.y);
            Ar[2*4 + c0i] = tf32r(la0.z); Ar[3*4 + c0i] = tf32r(la0.w);
            Ar[0*4 + c1i] = tf32r(la1.x); Ar[1*4 + c1i] = tf32r(la1.y);
            Ar[2*4 + c1i] = tf32r(la1.z); Ar[3*4 + c1i] = tf32r(la1.w);
            Br[0*4 + c0i] = lb0.x; Br[1*4 + c0i] = lb0.y;
            Br[2*4 + c0i] = lb0.z; Br[3*4 + c0i] = lb0.w;
            Br[0*4 + c1i] = lb1.x; Br[1*4 + c1i] = lb1.y;
            Br[2*4 + c1i] = lb1.z; Br[3*4 + c1i] = lb1.w;
        }
        __syncthreads();
        if (it + 1 < NIT) {
            int k0 = (it + 1) * 16;
            if (aok) { la0 = *(const float4*)(ap + k0); la1 = *(const float4*)(ap + k0 + 4); }
            lb0 = *(const float4*)(bp + k0);
            lb1 = *(const float4*)(bp + k0 + 4);
        }
        float4 va[2], vb[2];
        #pragma unroll
        for (int mt = 0; mt < 2; mt++) {
            int rr = wm * 32 + mt * 16 + g;
            va[mt] = *(float4*)&As[buf][rr][tig * 4];
            vb[mt] = *(float4*)&As[buf][rr + 8][tig * 4];
        }
        #pragma unroll
        for (int nt = 0; nt < 8; nt++) {
            int nn = wn * 64 + nt * 8 + g;
            float4 wv = *(float4*)&Bs[buf][nn][tig * 4];
            #pragma unroll
            for (int mt = 0; mt < 2; mt++) {
                mma_tf32(acc[mt][nt][0], acc[mt][nt][1], acc[mt][nt][2], acc[mt][nt][3],
                         va[mt].x, vb[mt].x, va[mt].y, vb[mt].y, wv.x, wv.y);
                mma_tf32(acc[mt][nt][0], acc[mt][nt][1], acc[mt][nt][2], acc[mt][nt][3],
                         va[mt].z, vb[mt].z, va[mt].w, vb[mt].w, wv.z, wv.w);
            }
        }
        __syncthreads();
    }

    #pragma unroll
    for (int mt = 0; mt < 2; mt++) {
        int r1 = row0 + wm * 32 + mt * 16 + g;
        int r2 = r1 + 8;
        #pragma unroll
        for (int nt = 0; nt < 8; nt++) {
            int cc = col0 + wn * 64 + nt * 8 + tig * 2;
            if (cc >= Nreal) continue;
            if (EPI == 1) {
                float b0 = X[cc], b1 = X[cc + 1];
                if (r1 < M) {
                    float v0 = acc[mt][nt][0] + b0, v1 = acc[mt][nt][1] + b1;
                    float* d = C + (long)r1 * ldc + cc;
                    d[0] = 0.5f * v0 * (1.f + erff(v0 * 0.70710678118654752f));
                    d[1] = 0.5f * v1 * (1.f + erff(v1 * 0.70710678118654752f));
                }
                if (r2 < M) {
                    float v2 = acc[mt][nt][2] + b0, v3 = acc[mt][nt][3] + b1;
                    float* d = C + (long)r2 * ldc + cc;
                    d[0] = 0.5f * v2 * (1.f + erff(v2 * 0.70710678118654752f));
                    d[1] = 0.5f * v3 * (1.f + erff(v3 * 0.70710678118654752f));
                }
            } else if (EPI == 2) {
                float sc = (cc < 64) ? 0.35355339059327373f : 1.f;
                if (r1 < M) {
                    float* d = C + (long)r1 * ldc + cc;
                    d[0] = acc[mt][nt][0] * sc; d[1] = acc[mt][nt][1] * sc;
                }
                if (r2 < M) {
                    float* d = C + (long)r2 * ldc + cc;
                    d[0] = acc[mt][nt][2] * sc; d[1] = acc[mt][nt][3] * sc;
                }
            } else {
                if (r1 < M) {
                    float* d = C + (long)r1 * ldc + cc;
                    d[0] += acc[mt][nt][0] + X[cc]; d[1] += acc[mt][nt][1] + X[cc + 1];
                }
                if (r2 < M) {
                    float* d = C + (long)r2 * ldc + cc;
                    d[0] += acc[mt][nt][2] + X[cc]; d[1] += acc[mt][nt][3] + X[cc + 1];
                }
            }
        }
    }
}

// ------------- batched 256^3 tf32 mma GEMM (pinv iters 0..4) ----------------
// C = c0*(A@B) + c1*X, all row-major [256][256] per head (blockIdx.z).
__global__ void __launch_bounds__(128) pinv_mma_kernel(
    const float* __restrict__ A, const float* __restrict__ B,
    float* __restrict__ C, const float* __restrict__ X,
    float c0, float c1)
{
    long off = (long)blockIdx.z * (LM * LM);
    A += off; B += off; C += off;
    const float* Xp = X ? X + off : (const float*)0;
    __shared__ float As[2][64][20];
    __shared__ float Bs[2][16][68];

    int tid = threadIdx.x;
    int lane = tid & 31, wid = tid >> 5;
    int g = lane >> 2, tig = lane & 3;
    int wm = wid & 1, wn = wid >> 1;
    int row0 = blockIdx.x * 64, col0 = blockIdx.y * 64;

    int lr = tid >> 1, ks = tid & 1;
    const float* ap = A + (row0 + lr) * LM + ks * 8;
    int kb = tid >> 4, nb = (tid & 15) * 4;
    const float* bp = B + kb * LM + col0 + nb;

    float acc[2][4][4];
    #pragma unroll
    for (int mt = 0; mt < 2; mt++)
        #pragma unroll
        for (int nt = 0; nt < 4; nt++)
            #pragma unroll
            for (int q = 0; q < 4; q++) acc[mt][nt][q] = 0.f;

    float4 la0 = *(const float4*)(ap), la1 = *(const float4*)(ap + 4);
    float4 lb0 = *(const float4*)(bp), lb1 = *(const float4*)(bp + 8 * LM);

    const int NIT = LM / 16;    // 16
    for (int it = 0; it < NIT; it++) {
        int buf = it & 1;
        {
            int c0i = ks * 2, c1i = ks * 2 + 1;
            float* Ar = &As[buf][lr][0];
            Ar[0*4 + c0i] = tf32r(la0.x); Ar[1*4 + c0i] = tf32r(la0.y);
            Ar[2*4 + c0i] = tf32r(la0.z); Ar[3*4 + c0i] = tf32r(la0.w);
            Ar[0*4 + c1i] = tf32r(la1.x); Ar[1*4 + c1i] = tf32r(la1.y);
            Ar[2*4 + c1i] = tf32r(la1.z); Ar[3*4 + c1i] = tf32r(la1.w);
            float* B0 = &Bs[buf][kb][nb];
            B0[0] = tf32r(lb0.x); B0[1] = tf32r(lb0.y); B0[2] = tf32r(lb0.z); B0[3] = tf32r(lb0.w);
            float* B1 = &Bs[buf][kb + 8][nb];
            B1[0] = tf32r(lb1.x); B1[1] = tf32r(lb1.y); B1[2] = tf32r(lb1.z); B1[3] = tf32r(lb1.w);
        }
        __syncthreads();
        if (it + 1 < NIT) {
            int k0 = (it + 1) * 16;
            la0 = *(const float4*)(ap + k0); la1 = *(const float4*)(ap + k0 + 4);
            lb0 = *(const float4*)(bp + k0 * LM); lb1 = *(const float4*)(bp + (k0 + 8) * LM);
        }
        float4 va[2], vb[2];
        #pragma unroll
        for (int mt = 0; mt < 2; mt++) {
            int rr = wm * 32 + mt * 16 + g;
            va[mt] = *(float4*)&As[buf][rr][tig * 4];
            vb[mt] = *(float4*)&As[buf][rr + 8][tig * 4];
        }
        #pragma unroll
        for (int nt = 0; nt < 4; nt++) {
            int nn = wn * 32 + nt * 8 + g;
            float b0 = Bs[buf][tig][nn];
            float b1 = Bs[buf][tig + 4][nn];
            float b2 = Bs[buf][tig + 8][nn];
            float b3 = Bs[buf][tig + 12][nn];
            #pragma unroll
            for (int mt = 0; mt < 2; mt++) {
                mma_tf32(acc[mt][nt][0], acc[mt][nt][1], acc[mt][nt][2], acc[mt][nt][3],
                         va[mt].x, vb[mt].x, va[mt].y, vb[mt].y, b0, b1);
                mma_tf32(acc[mt][nt][0], acc[mt][nt][1], acc[mt][nt][2], acc[mt][nt][3],
                         va[mt].z, vb[mt].z, va[mt].w, vb[mt].w, b2, b3);
            }
        }
        __syncthreads();
    }

    #pragma unroll
    for (int mt = 0; mt < 2; mt++) {
        int r1 = row0 + wm * 32 + mt * 16 + g;
        int r2 = r1 + 8;
        #pragma unroll
        for (int nt = 0; nt < 4; nt++) {
            int cc = col0 + wn * 32 + nt * 8 + tig * 2;
            long i1 = (long)r1 * LM + cc, i2 = (long)r2 * LM + cc;
            float v0 = c0 * acc[mt][nt][0], v1 = c0 * acc[mt][nt][1];
            float v2 = c0 * acc[mt][nt][2], v3 = c0 * acc[mt][nt][3];
            if (c1 != 0.f) {
                v0 += c1 * Xp[i1]; v1 += c1 * Xp[i1 + 1];
                v2 += c1 * Xp[i2]; v3 += c1 * Xp[i2 + 1];
            }
            C[i1] = v0; C[i1 + 1] = v1; C[i2] = v2; C[i2 + 1] = v3;
        }
    }
}

// -------------------- fp32 batched 256^3 GEMM (final pinv iter) -------------
__global__ void __launch_bounds__(256) sgemm64_kernel(
    const float* __restrict__ A, const float* __restrict__ B,
    float* __restrict__ C, const float* __restrict__ X,
    float c0, float c1)
{
    long off = (long)blockIdx.z * (LM*LM);
    A += off; B += off; C += off;
    const float* Xp = X ? X + off : (const float*)0;
    __shared__ float As[2][16][64];
    __shared__ float Bs[2][16][64];
    int row0 = blockIdx.x * 64, col0 = blockIdx.y * 64;
    int tid = threadIdx.x;
    int tx = tid & 15, ty = tid >> 4;
    int ar = tid >> 2, ac = (tid & 3) * 4;
    int br = tid >> 4, bc = (tid & 15) * 4;

    const float* Aptr = A + (row0 + ar) * LM + ac;
    const float* Bptr = B + br * LM + col0 + bc;

    float acc[4][4];
    #pragma unroll
    for (int i=0;i<4;i++)
        #pragma unroll
        for (int j=0;j<4;j++) acc[i][j]=0.f;

    float4 a4 = *(const float4*)(Aptr);
    float4 b4 = *(const float4*)(Bptr);
    As[0][ac+0][ar]=a4.x; As[0][ac+1][ar]=a4.y; As[0][ac+2][ar]=a4.z; As[0][ac+3][ar]=a4.w;
    *(float4*)&Bs[0][br][bc] = b4;
    __syncthreads();

    const int nk = LM / 16;
    for (int t = 0; t < nk; t++) {
        int buf = t & 1;
        float4 na, nb;
        if (t + 1 < nk) {
            int k0 = (t + 1) * 16;
            na = *(const float4*)(Aptr + k0);
            nb = *(const float4*)(Bptr + k0 * LM);
        }
        #pragma unroll
        for (int kk=0; kk<16; kk++) {
            float a0[4], b0[4];
            *(float4*)&a0[0] = *(float4*)&As[buf][kk][ty*4];
            *(float4*)&b0[0] = *(float4*)&Bs[buf][kk][tx*4];
            #pragma unroll
            for (int i=0;i<4;i++)
                #pragma unroll
                for (int j=0;j<4;j++) acc[i][j] += a0[i]*b0[j];
        }
        if (t + 1 < nk) {
            int nb_ = buf ^ 1;
            As[nb_][ac+0][ar]=na.x; As[nb_][ac+1][ar]=na.y;
            As[nb_][ac+2][ar]=na.z; As[nb_][ac+3][ar]=na.w;
            *(float4*)&Bs[nb_][br][bc] = nb;
            __syncthreads();
        }
    }
    #pragma unroll
    for (int i=0;i<4;i++) {
        int r = row0 + ty*4 + i;
        #pragma unroll
        for (int j=0;j<4;j++) {
            int c = col0 + tx*4 + j;
            long idx = (long)r * LM + c;
            float v = c0 * acc[i][j];
            if (c1 != 0.f) v += c1 * Xp[idx];
            C[idx] = v;
        }
    }
}

// ------------------------------ helpers ------------------------------------
static __device__ __forceinline__ float blockSum128(float v) {
    __shared__ float sh[4];
    #pragma unroll
    for (int o = 16; o; o >>= 1) v += __shfl_xor_sync(0xffffffffu, v, o);
    __syncthreads();
    if ((threadIdx.x & 31) == 0) sh[threadIdx.x >> 5] = v;
    __syncthreads();
    return sh[0] + sh[1] + sh[2] + sh[3];
}

// ------------------------------ layernorm -----------------------------------
__global__ void ln_pad_kernel(const float* __restrict__ in, float* __restrict__ out,
                              const float* __restrict__ g, const float* __restrict__ b)
{
    int p = blockIdx.x;
    int tid = threadIdx.x;
    float* orow = out + (long)p * HID;
    if (p < PADR) {
        *(float4*)(orow + tid*4) = make_float4(0.f,0.f,0.f,0.f);
        return;
    }
    const float* x = in + (long)(p - PADR) * HID;
    float4 v = *(const float4*)(x + tid*4);
    float s = blockSum128(v.x+v.y+v.z+v.w);
    float mu = s * (1.f/512.f);
    float d0=v.x-mu, d1=v.y-mu, d2=v.z-mu, d3=v.w-mu;
    float sq = blockSum128(d0*d0+d1*d1+d2*d2+d3*d3);
    float rstd = rsqrtf(sq*(1.f/512.f) + 1e-5f);
    int c = tid*4;
    orow[c+0]=d0*rstd*g[c+0]+b[c+0]; orow[c+1]=d1*rstd*g[c+1]+b[c+1];
    orow[c+2]=d2*rstd*g[c+2]+b[c+2]; orow[c+3]=d3*rstd*g[c+3]+b[c+3];
}

__global__ void final_ln_kernel(const float* __restrict__ in,
                                const float* __restrict__ g, const float* __restrict__ b,
                                float* __restrict__ out)
{
    int tid = threadIdx.x;
    float4 v = *(const float4*)(in + tid*4);
    float s = blockSum128(v.x+v.y+v.z+v.w);
    float mu = s * (1.f/512.f);
    float d0=v.x-mu, d1=v.y-mu, d2=v.z-mu, d3=v.w-mu;
    float sq = blockSum128(d0*d0+d1*d1+d2*d2+d3*d3);
    float rstd = rsqrtf(sq*(1.f/512.f) + 1e-5f);
    int c = tid*4;
    out[c+0]=d0*rstd*g[c+0]+b[c+0]; out[c+1]=d1*rstd*g[c+1]+b[c+1];
    out[c+2]=d2*rstd*g[c+2]+b[c+2]; out[c+3]=d3*rstd*g[c+3]+b[c+3];
}

// ------------------------------ landmarks -----------------------------------
__global__ void landmark_kernel()
{
    int i = blockIdx.x;
    int c = threadIdx.x;
    const float* base = g_qkv + (long)i * LSEG * QKV3 + c;
    float s = 0.f;
    #pragma unroll 7
    for (int t = 0; t < LSEG; t++) s += base[(long)t * QKV3];
    s *= (1.f/77.f);
    if (c < 64) g_ql[((c>>3)*LM + i)*DH + (c&7)] = s;
    else { int c2 = c-64; g_kl[((c2>>3)*LM + i)*DH + (c2&7)] = s; }
}

// --------------------------- attn2 + softmax --------------------------------
__global__ void attn2_kernel()
{
    int i = blockIdx.x, h = blockIdx.y;
    int j = threadIdx.x;
    __shared__ float red[256];
    const float* qi = g_ql + (h*LM + i)*DH;
    const float* kj = g_kl + (h*LM + j)*DH;
    float dot = 0.f;
    #pragma unroll
    for (int d = 0; d < DH; d++) dot += qi[d]*kj[d];
    red[j] = dot; __syncthreads();
    for (int s = 128; s > 0; s >>= 1) { if (j < s) red[j] = fmaxf(red[j], red[j+s]); __syncthreads(); }
    float m = red[0]; __syncthreads();
    float p = expf(dot - m);
    red[j] = p; __syncthreads();
    for (int s = 128; s > 0; s >>= 1) { if (j < s) red[j] += red[j+s]; __syncthreads(); }
    g_a2[(h*LM + i)*LM + j] = p / red[0];
}

__global__ void zero_scale_kernel() { g_scale_bits = 0u; }

__global__ void colmax_kernel()
{
    int h = blockIdx.x, j = threadIdx.x;
    __shared__ float red[256];
    const float* col = g_a2 + h*(LM*LM) + j;
    float s = 0.f;
    for (int i = 0; i < LM; i++) s += col[i*LM];
    red[j] = s; __syncthreads();
    for (int k = 128; k > 0; k >>= 1) { if (j < k) red[j] = fmaxf(red[j], red[j+k]); __syncthreads(); }
    if (j == 0) atomicMax(&g_scale_bits, __float_as_uint(red[0]));
}

__global__ void zinit_kernel()
{
    int i = blockIdx.x, h = blockIdx.y, j = threadIdx.x;
    float scale = __uint_as_float(g_scale_bits);
    g_z0[h*(LM*LM) + i*LM + j] = g_a2[h*(LM*LM) + j*LM + i] / scale;
}

// --------------------------- attn3 @ v (flash) ------------------------------
__global__ void __launch_bounds__(256) attn3_kernel()
{
    int h = blockIdx.y;
    int tid = threadIdx.x;
    int lmi = tid >> 3, sub = tid & 7;
    int L0 = blockIdx.x * 32 + lmi;
    __shared__ float kt[256][9];
    __shared__ float vt[256][9];

    float q[8];
    #pragma unroll
    for (int d = 0; d < 8; d++) q[d] = g_ql[(h*LM + L0)*DH + d];

    float m = -1e30f;
    for (int t0 = 0; t0 < NP; t0 += 256) {
        const float* kr = g_qkv + (long)(t0 + tid) * QKV3 + 64 + h*8;
        #pragma unroll
        for (int d = 0; d < 8; d++) kt[tid][d] = kr[d];
        __syncthreads();
        for (int j = sub; j < 256; j += 8) {
            float dot = 0.f;
            #pragma unroll
            for (int d = 0; d < 8; d++) dot += q[d]*kt[j][d];
            m = fmaxf(m, dot);
        }
        __syncthreads();
    }
    #pragma unroll
    for (int o = 4; o; o >>= 1) m = fmaxf(m, __shfl_xor_sync(0xffffffffu, m, o));

    float s = 0.f, acc[8];
    #pragma unroll
    for (int d = 0; d < 8; d++) acc[d] = 0.f;
    for (int t0 = 0; t0 < NP; t0 += 256) {
        const float* kr = g_qkv + (long)(t0 + tid) * QKV3 + 64 + h*8;
        #pragma unroll
        for (int d = 0; d < 8; d++) { kt[tid][d] = kr[d]; vt[tid][d] = kr[64+d]; }
        __syncthreads();
        for (int j = sub; j < 256; j += 8) {
            float dot = 0.f;
            #pragma unroll
            for (int d = 0; d < 8; d++) dot += q[d]*kt[j][d];
            float p = expf(dot - m);
            s += p;
            #pragma unroll
            for (int d = 0; d < 8; d++) acc[d] += p * vt[j][d];
        }
        __syncthreads();
    }
    #pragma unroll
    for (int o = 4; o; o >>= 1) {
        s += __shfl_xor_sync(0xffffffffu, s, o);
        #pragma unroll
        for (int d = 0; d < 8; d++) acc[d] += __shfl_xor_sync(0xffffffffu, acc[d], o);
    }
    if (sub == 0) {
        float inv = 1.f / s;
        #pragma unroll
        for (int d = 0; d < 8; d++) g_av[(h*LM + L0)*DH + d] = acc[d]*inv;
    }
}

// --------------------------- W = pinv(a2) @ av ------------------------------
__global__ void wmat_kernel()
{
    int h = blockIdx.x, r = threadIdx.x;
    __shared__ float avs[256][8];
    #pragma unroll
    for (int d = 0; d < 8; d++) avs[r][d] = g_av[(h*LM + r)*DH + d];
    __syncthreads();
    const float* zr = g_z0 + h*(LM*LM) + r*LM;
    float acc[8];
    #pragma unroll
    for (int d = 0; d < 8; d++) acc[d] = 0.f;
    for (int k = 0; k < LM; k++) {
        float zv = zr[k];
        #pragma unroll
        for (int d = 0; d < 8; d++) acc[d] += zv * avs[k][d];
    }
    #pragma unroll
    for (int d = 0; d < 8; d++) g_W[(h*LM + r)*DH + d] = acc[d];
}

// ----------------------- attn1 @ W + dwconv(v) ------------------------------
__global__ void __launch_bounds__(256) attn1_kernel(const float* __restrict__ resw)
{
    int h = blockIdx.y;
    int tid = threadIdx.x;
    int i = blockIdx.x * 256 + tid;
    __shared__ float kl[256][8];
    __shared__ float Wm[256][8];
    __shared__ float cw[33];
    {
        const float* ks = g_kl + (h*LM + tid)*DH;
        const float* ws = g_W  + (h*LM + tid)*DH;
        *(float4*)&kl[tid][0] = *(const float4*)(ks);
        *(float4*)&kl[tid][4] = *(const float4*)(ks+4);
        *(float4*)&Wm[tid][0] = *(const float4*)(ws);
        *(float4*)&Wm[tid][4] = *(const float4*)(ws+4);
        if (tid < 33) cw[tid] = resw[h*33 + tid];
    }
    __syncthreads();
    if (i >= NSEQ) return;
    int t = PADR + i;
    float q[8];
    {
        const float* qr = g_qkv + (long)t * QKV3 + h*8;
        #pragma unroll
        for (int d = 0; d < 8; d++) q[d] = qr[d];
    }
    float m = -1e30f;
    for (int j = 0; j < 256; j++) {
        float4 k0 = *(float4*)&kl[j][0];
        float4 k1 = *(float4*)&kl[j][4];
        float dot = q[0]*k0.x + q[1]*k0.y + q[2]*k0.z + q[3]*k0.w
                  + q[4]*k1.x + q[5]*k1.y + q[6]*k1.z + q[7]*k1.w;
        m = fmaxf(m, dot);
    }
    float s = 0.f, acc[8];
    #pragma unroll
    for (int d = 0; d < 8; d++) acc[d] = 0.f;
    for (int j = 0; j < 256; j++) {
        float4 k0 = *(float4*)&kl[j][0];
        float4 k1 = *(float4*)&kl[j][4];
        float dot = q[0]*k0.x + q[1]*k0.y + q[2]*k0.z + q[3]*k0.w
                  + q[4]*k1.x + q[5]*k1.y + q[6]*k1.z + q[7]*k1.w;
        float p = expf(dot - m);
        s += p;
        float4 w0 = *(float4*)&Wm[j][0];
        float4 w1 = *(float4*)&Wm[j][4];
        acc[0]+=p*w0.x; acc[1]+=p*w0.y; acc[2]+=p*w0.z; acc[3]+=p*w0.w;
        acc[4]+=p*w1.x; acc[5]+=p*w1.y; acc[6]+=p*w1.z; acc[7]+=p*w1.w;
    }
    float inv = 1.f / s;
    float o[8];
    #pragma unroll
    for (int d = 0; d < 8; d++) o[d] = acc[d]*inv;
    #pragma unroll 4
    for (int k = 0; k < 33; k++) {
        int r = t + k - 16;
        if (r < NP) {
            const float* vr = g_qkv + (long)r * QKV3 + 128 + h*8;
            float4 v0 = *(const float4*)(vr);
            float4 v1 = *(const float4*)(vr+4);
            float c = cw[k];
            o[0]+=c*v0.x; o[1]+=c*v0.y; o[2]+=c*v0.z; o[3]+=c*v0.w;
            o[4]+=c*v1.x; o[5]+=c*v1.y; o[6]+=c*v1.z; o[7]+=c*v1.w;
        }
    }
    float* outp = g_attnout + (long)i * INNER + h*8;
    *(float4*)(outp)   = make_float4(o[0],o[1],o[2],o[3]);
    *(float4*)(outp+4) = make_float4(o[4],o[5],o[6],o[7]);
}

// ------------------------------ PPEG ----------------------------------------
__global__ void ppeg_prep(const float* __restrict__ w7, const float* __restrict__ b7,
                          const float* __restrict__ w5, const float* __restrict__ b5,
                          const float* __restrict__ w3, const float* __restrict__ b3)
{
    int c = blockIdx.x;
    int k = threadIdx.x;
    if (k < 49) {
        int dy = k/7 - 3, dx = k%7 - 3;
        float w = w7[c*49 + k];
        if (dy >= -2 && dy <= 2 && dx >= -2 && dx <= 2) w += w5[c*25 + (dy+2)*5 + (dx+2)];
        if (dy >= -1 && dy <= 1 && dx >= -1 && dx <= 1) w += w3[c*9 + (dy+1)*3 + (dx+1)];
        if (dy == 0 && dx == 0) w += 1.f;
        g_wcomb[k*HID + c] = w;
    }
    if (k == 0) g_bcomb[c] = b7[c] + b5[c] + b3[c];
}

__global__ void __launch_bounds__(256) ppeg_kernel()
{
    int cg = blockIdx.z;
    int px0 = blockIdx.x*8, py0 = blockIdx.y*8;
    int tid = threadIdx.x;
    int cl = tid & 31, pidx = tid >> 5;
    __shared__ float insh[14][14][32];
    __shared__ float wsh[49][32];
    __shared__ float bsh[32];
    for (int idx = tid; idx < 14*14*32; idx += 256) {
        int ch = idx & 31; int pos = idx >> 5;
        int iy = pos/14, ix = pos%14;
        int gy = py0 + iy - 3, gx = px0 + ix - 3;
        float v = 0.f;
        if (gy >= 0 && gy < 140 && gx >= 0 && gx < 140)
            v = g_h[(long)(1 + gy*140 + gx)*HID + cg*32 + ch];
        insh[iy][ix][ch] = v;
    }
    for (int idx = tid; idx < 49*32; idx += 256) {
        int ch = idx & 31, k = idx >> 5;
        wsh[k][ch] = g_wcomb[k*HID + cg*32 + ch];
    }
    if (tid < 32) bsh[tid] = g_bcomb[cg*32 + tid];
    __syncthreads();

    int c = cg*32 + cl;
    int gx = px0 + pidx;
    if (gx >= 140) return;
    for (int yy = 0; yy < 8; yy++) {
        int gy = py0 + yy;
        if (gy >= 140) break;
        float acc = bsh[cl];
        #pragma unroll
        for (int dy = 0; dy < 7; dy++)
            #pragma unroll
            for (int dx = 0; dx < 7; dx++)
                acc += wsh[dy*7+dx][cl] * insh[yy+dy][pidx+dx][cl];
        g_hb[(long)(1 + gy*140 + gx)*HID + c] = acc;
    }
}

__global__ void copy_cls(const float* __restrict__ src, float* __restrict__ dst)
{
    int t = threadIdx.x;
    dst[t] = src[t];
    dst[t+256] = src[t+256];
}

// ------------------------------ host orchestration --------------------------
extern "C" void kernel_launch(void* const* d_in, const int* in_sizes, int n_in,
                              void* d_out, int out_size)
{
    (void)in_sizes; (void)n_in; (void)out_size;
    const float* x       = (const float*)d_in[0];
    const float* fc1_w   = (const float*)d_in[1];
    const float* fc1_b   = (const float*)d_in[2];
    const float* cls_tok = (const float*)d_in[3];
    const float* l_ng[2] = {(const float*)d_in[4],  (const float*)d_in[10]};
    const float* l_nb[2] = {(const float*)d_in[5],  (const float*)d_in[11]};
    const float* l_qw[2] = {(const float*)d_in[6],  (const float*)d_in[12]};
    const float* l_ow[2] = {(const float*)d_in[7],  (const float*)d_in[13]};
    const float* l_ob[2] = {(const float*)d_in[8],  (const float*)d_in[14]};
    const float* l_rw[2] = {(const float*)d_in[9],  (const float*)d_in[15]};
    const float* p7w = (const float*)d_in[16];
    const float* p7b = (const float*)d_in[17];
    const float* p5w = (const float*)d_in[18];
    const float* p5b = (const float*)d_in[19];
    const float* p3w = (const float*)d_in[20];
    const float* p3b = (const float*)d_in[21];
    const float* norm_g = (const float*)d_in[22];
    const float* norm_b = (const float*)d_in[23];

    float *h, *hb, *xpad, *qkv, *attnout, *a2, *z0, *z1, *az, *t1, *t2;
    float *wT, *qkvT, *owT;
    cudaGetSymbolAddress((void**)&h,  g_h);
    cudaGetSymbolAddress((void**)&hb, g_hb);
    cudaGetSymbolAddress((void**)&xpad, g_xpad);
    cudaGetSymbolAddress((void**)&qkv,  g_qkv);
    cudaGetSymbolAddress((void**)&attnout, g_attnout);
    cudaGetSymbolAddress((void**)&a2, g_a2);
    cudaGetSymbolAddress((void**)&z0, g_z0);
    cudaGetSymbolAddress((void**)&z1, g_z1);
    cudaGetSymbolAddress((void**)&az, g_az);
    cudaGetSymbolAddress((void**)&t1, g_t1m);
    cudaGetSymbolAddress((void**)&t2, g_t2m);
    cudaGetSymbolAddress((void**)&wT, g_wT);
    cudaGetSymbolAddress((void**)&qkvT, g_qkvT);
    cudaGetSymbolAddress((void**)&owT, g_owT);

    // fc1 + GELU via mma.sync tf32 -> rows 1.. of g_h; cls -> row 0
    transpose_pad_kernel<<<dim3(IND/32, HID/32), dim3(32,8)>>>(fc1_w, wT, IND, HID);
    gemm_mma_kernel<1><<<dim3(154, 4), 256>>>(x, wT, h + HID, fc1_b,
                                              NTOK, HID, IND, IND, HID);
    copy_cls<<<1,256>>>(cls_tok, h);

    for (int layer = 0; layer < 2; layer++) {
        float* hcur = (layer == 0) ? h : hb;

        ln_pad_kernel<<<NP,128>>>(hcur, xpad, l_ng[layer], l_nb[layer]);
        transpose_pad_kernel<<<dim3(HID/32, 256/32), dim3(32,8)>>>(l_qw[layer], qkvT, HID, QKV3);
        gemm_mma_kernel<2><<<dim3(154, 2), 256>>>(xpad, qkvT, qkv, (const float*)0,
                                                  NP, QKV3, HID, HID, QKV3);
        landmark_kernel<<<LM,128>>>();
        attn2_kernel<<<dim3(LM,HEADS),256>>>();
        zero_scale_kernel<<<1,1>>>();
        colmax_kernel<<<HEADS,256>>>();
        zinit_kernel<<<dim3(LM,HEADS),256>>>();
        attn3_kernel<<<dim3(8,HEADS),256>>>();

        for (int it = 0; it < 6; it++) {
            float* zin  = (it & 1) ? z1 : z0;
            float* zout = (it & 1) ? z0 : z1;
            dim3 gp(4,4,HEADS);
            if (it < 5) {
                pinv_mma_kernel<<<gp,128>>>(a2, zin, az, (const float*)0, 1.f, 0.f);
                pinv_mma_kernel<<<gp,128>>>(az, az, t1, az, -1.f, 7.f);
                pinv_mma_kernel<<<gp,128>>>(az, t1, t2, az, -1.f, 15.f);
                pinv_mma_kernel<<<gp,128>>>(zin, t2, zout, zin, -0.25f, 3.25f);
            } else {   // final iteration in fp32 (Newton self-correction)
                sgemm64_kernel<<<gp,256>>>(a2, zin, az, (const float*)0, 1.f, 0.f);
                sgemm64_kernel<<<gp,256>>>(az, az, t1, az, -1.f, 7.f);
                sgemm64_kernel<<<gp,256>>>(az, t1, t2, az, -1.f, 15.f);
                sgemm64_kernel<<<gp,256>>>(zin, t2, zout, zin, -0.25f, 3.25f);
            }
        }
        wmat_kernel<<<HEADS,256>>>();
        attn1_kernel<<<dim3(77,HEADS),256>>>(l_rw[layer]);
        transpose_pad_kernel<<<dim3(INNER/32, HID/32), dim3(32,8)>>>(l_ow[layer], owT, INNER, HID);
        gemm_mma_kernel<3><<<dim3(154, 4), 256>>>(attnout, owT, hcur, l_ob[layer],
                                                  NSEQ, HID, INNER, INNER, HID);
        if (layer == 0) {
            ppeg_prep<<<HID,64>>>(p7w, p7b, p5w, p5b, p3w, p3b);
            ppeg_kernel<<<dim3(18,18,16),256>>>();
            copy_cls<<<1,256>>>(h, hb);
        }
    }
    final_ln_kernel<<<1,128>>>(hb, norm_g, norm_b, (float*)d_out);
}

// round 12
// speedup vs baseline: 1.5762x; 1.2575x over previous
#include <cuda_runtime.h>
#include <cuda_fp16.h>
#include <math.h>
#include <stdint.h>

#define NTOK   19600
#define NSEQ   19601
#define PADR   111
#define NP     19712
#define HID    512
#define IND    1024
#define QKV3   192
#define HEADS  8
#define DH     8
#define INNER  64
#define LM     256
#define LSEG   77

// ------------------------- scratch (device globals) ------------------------
__device__ float g_h   [NSEQ * HID];
__device__ float g_hb  [NSEQ * HID];
__device__ float g_xpad[NP * HID];
__device__ float g_qkv [NP * QKV3];
__device__ float g_attnout[NSEQ * INNER];
__device__ float g_ql  [HEADS * LM * DH];
__device__ float g_kl  [HEADS * LM * DH];
__device__ float g_a2  [HEADS * LM * LM];
__device__ float g_z0  [HEADS * LM * LM];
__device__ float g_z1  [HEADS * LM * LM];
__device__ float g_az  [HEADS * LM * LM];
__device__ float g_t1m [HEADS * LM * LM];
__device__ float g_t2m [HEADS * LM * LM];
__device__ float g_av  [HEADS * LM * DH];
__device__ float g_W   [HEADS * LM * DH];
__device__ unsigned int g_scale_bits;
__device__ float g_wcomb[49 * HID];
__device__ float g_bcomb[HID];
__device__ float g_wT  [HID * IND];      // fc1_w^T  [512][1024]
__device__ float g_qkvT[256 * HID];      // qkv_w^T  [256(pad)][512]
__device__ float g_owT [HID * INNER];    // out_w^T  [512][64]

static __device__ __forceinline__ uint32_t h2pack(float a, float b) {
    __half2 h = __floats2half2_rn(a, b);
    return *(uint32_t*)&h;
}

// one m16n8k16 fp16 mma.sync (fp32 accumulate)
static __device__ __forceinline__ void mma_f16(
    float& c0, float& c1, float& c2, float& c3,
    uint32_t a0, uint32_t a1, uint32_t a2, uint32_t a3,
    uint32_t b0, uint32_t b1)
{
    asm volatile(
        "mma.sync.aligned.m16n8k16.row.col.f32.f16.f16.f32 "
        "{%0,%1,%2,%3}, {%4,%5,%6,%7}, {%8,%9}, {%0,%1,%2,%3};"
        : "+f"(c0), "+f"(c1), "+f"(c2), "+f"(c3)
        : "r"(a0), "r"(a1), "r"(a2), "r"(a3), "r"(b0), "r"(b1));
}

// ------------------- generic transpose + pad --------------------------------
// w [K][N] -> wt [Npad][K] (Npad = gridDim.y*32), zero-filled for n >= N.
__global__ void transpose_pad_kernel(const float* __restrict__ w, float* __restrict__ wt,
                                     int K, int N)
{
    __shared__ float t[32][33];
    int k0 = blockIdx.x * 32, n0 = blockIdx.y * 32;
    int tx = threadIdx.x, ty = threadIdx.y;        // 32 x 8
    #pragma unroll
    for (int i = ty; i < 32; i += 8)
        t[i][tx] = (n0 + tx < N) ? w[(long)(k0 + i) * N + n0 + tx] : 0.f;
    __syncthreads();
    #pragma unroll
    for (int i = ty; i < 32; i += 8)
        wt[(long)(n0 + i) * K + k0 + tx] = t[tx][i];
}

// -------- generic fp16 mma GEMM: 128x128 tile, BK=16, 256 thr ---------------
// C[m][n] = sum_k A[m][k] * BT[n][k]   (BT pre-transposed)
// SMEM rows: 8 half2 slots, permuted: slot 2t = k-pair t, slot 2t+1 = k-pair t+4.
// EPI: 1 bias+GELU | 2 qkv q-scale | 3 C += acc + X (residual)
template <int EPI>
__global__ void __launch_bounds__(256) gemm_mma_kernel(
    const float* __restrict__ A, const float* __restrict__ BT,
    float* __restrict__ C, const float* __restrict__ X,
    int M, int Nreal, int K, int lda, int ldc)
{
    __shared__ __align__(16) uint32_t As[2][128][10];
    __shared__ __align__(16) uint32_t Bs[2][128][10];

    int tid  = threadIdx.x;
    int lane = tid & 31, wid = tid >> 5;
    int g = lane >> 2, tig = lane & 3;
    int wm = wid & 3, wn = wid >> 2;
    int row0 = blockIdx.x * 128, col0 = blockIdx.y * 128;

    bool isA = tid < 128;
    int lr = isA ? tid : tid - 128;
    bool lok = isA ? (row0 + lr < M) : true;
    const float* lp = isA ? (A + (long)(row0 + lr) * lda)
                          : (BT + (long)(col0 + lr) * K);

    float acc[2][8][4];
    #pragma unroll
    for (int mt = 0; mt < 2; mt++)
        #pragma unroll
        for (int nt = 0; nt < 8; nt++)
            #pragma unroll
            for (int q = 0; q < 4; q++) acc[mt][nt][q] = 0.f;

    float4 f0 = make_float4(0,0,0,0), f1 = f0, f2 = f0, f3 = f0;
    if (lok) {
        f0 = *(const float4*)(lp + 0);  f1 = *(const float4*)(lp + 4);
        f2 = *(const float4*)(lp + 8);  f3 = *(const float4*)(lp + 12);
    }

    const int NIT = K / 16;
    for (int it = 0; it < NIT; it++) {
        int buf = it & 1;
        {
            uint32_t* R = isA ? &As[buf][lr][0] : &Bs[buf][lr][0];
            R[0] = h2pack(f0.x, f0.y); R[2] = h2pack(f0.z, f0.w);
            R[4] = h2pack(f1.x, f1.y); R[6] = h2pack(f1.z, f1.w);
            R[1] = h2pack(f2.x, f2.y); R[3] = h2pack(f2.z, f2.w);
            R[5] = h2pack(f3.x, f3.y); R[7] = h2pack(f3.z, f3.w);
        }
        __syncthreads();
        if (it + 1 < NIT) {
            int k0 = (it + 1) * 16;
            if (lok) {
                f0 = *(const float4*)(lp + k0 + 0);  f1 = *(const float4*)(lp + k0 + 4);
                f2 = *(const float4*)(lp + k0 + 8);  f3 = *(const float4*)(lp + k0 + 12);
            }
        }
        uint2 A0[2], A1[2];
        #pragma unroll
        for (int mt = 0; mt < 2; mt++) {
            int rr = wm * 32 + mt * 16 + g;
            A0[mt] = *(uint2*)&As[buf][rr][tig * 2];
            A1[mt] = *(uint2*)&As[buf][rr + 8][tig * 2];
        }
        #pragma unroll
        for (int nt = 0; nt < 8; nt++) {
            int nn = wn * 64 + nt * 8 + g;
            uint2 Bv = *(uint2*)&Bs[buf][nn][tig * 2];
            #pragma unroll
            for (int mt = 0; mt < 2; mt++)
                mma_f16(acc[mt][nt][0], acc[mt][nt][1], acc[mt][nt][2], acc[mt][nt][3],
                        A0[mt].x, A1[mt].x, A0[mt].y, A1[mt].y, Bv.x, Bv.y);
        }
        __syncthreads();
    }

    #pragma unroll
    for (int mt = 0; mt < 2; mt++) {
        int r1 = row0 + wm * 32 + mt * 16 + g;
        int r2 = r1 + 8;
        #pragma unroll
        for (int nt = 0; nt < 8; nt++) {
            int cc = col0 + wn * 64 + nt * 8 + tig * 2;
            if (cc >= Nreal) continue;
            if (EPI == 1) {
                float b0 = X[cc], b1 = X[cc + 1];
                if (r1 < M) {
                    float v0 = acc[mt][nt][0] + b0, v1 = acc[mt][nt][1] + b1;
                    float* d = C + (long)r1 * ldc + cc;
                    d[0] = 0.5f * v0 * (1.f + erff(v0 * 0.70710678118654752f));
                    d[1] = 0.5f * v1 * (1.f + erff(v1 * 0.70710678118654752f));
                }
                if (r2 < M) {
                    float v2 = acc[mt][nt][2] + b0, v3 = acc[mt][nt][3] + b1;
                    float* d = C + (long)r2 * ldc + cc;
                    d[0] = 0.5f * v2 * (1.f + erff(v2 * 0.70710678118654752f));
                    d[1] = 0.5f * v3 * (1.f + erff(v3 * 0.70710678118654752f));
                }
            } else if (EPI == 2) {
                float sc = (cc < 64) ? 0.35355339059327373f : 1.f;
                if (r1 < M) {
                    float* d = C + (long)r1 * ldc + cc;
                    d[0] = acc[mt][nt][0] * sc; d[1] = acc[mt][nt][1] * sc;
                }
                if (r2 < M) {
                    float* d = C + (long)r2 * ldc + cc;
                    d[0] = acc[mt][nt][2] * sc; d[1] = acc[mt][nt][3] * sc;
                }
            } else {
                if (r1 < M) {
                    float* d = C + (long)r1 * ldc + cc;
                    d[0] += acc[mt][nt][0] + X[cc]; d[1] += acc[mt][nt][1] + X[cc + 1];
                }
                if (r2 < M) {
                    float* d = C + (long)r2 * ldc + cc;
                    d[0] += acc[mt][nt][2] + X[cc]; d[1] += acc[mt][nt][3] + X[cc + 1];
                }
            }
        }
    }
}

// ------------- batched 256^3 fp16 mma GEMM (pinv iters 0..4) ----------------
// C = c0*(A@B) + c1*X, all row-major [256][256] per head (blockIdx.z).
__global__ void __launch_bounds__(128) pinv_mma_kernel(
    const float* __restrict__ A, const float* __restrict__ B,
    float* __restrict__ C, const float* __restrict__ X,
    float c0, float c1)
{
    long off = (long)blockIdx.z * (LM * LM);
    A += off; B += off; C += off;
    const float* Xp = X ? X + off : (const float*)0;
    __shared__ __align__(16) uint32_t As[2][64][10];
    __shared__ __align__(16) uint32_t Bs[2][8][72];   // Bs[kp][n] = half2(k=2kp, k=2kp+1)

    int tid = threadIdx.x;
    int lane = tid & 31, wid = tid >> 5;
    int g = lane >> 2, tig = lane & 3;
    int wm = wid & 1, wn = wid >> 1;
    int row0 = blockIdx.x * 64, col0 = blockIdx.y * 64;

    bool isA = tid < 64;
    int alr = tid;                       // A row (if isA)
    int bkp = (tid - 64) >> 3;           // B k-pair 0..7
    int bc0 = ((tid - 64) & 7) * 8;      // B col start (8 cols)
    const float* ap = A + (row0 + alr) * LM;
    const float* bp0 = B + (2 * bkp) * LM + col0 + bc0;
    const float* bp1 = B + (2 * bkp + 1) * LM + col0 + bc0;

    float acc[2][4][4];
    #pragma unroll
    for (int mt = 0; mt < 2; mt++)
        #pragma unroll
        for (int nt = 0; nt < 4; nt++)
            #pragma unroll
            for (int q = 0; q < 4; q++) acc[mt][nt][q] = 0.f;

    float4 f0, f1, f2, f3;
    if (isA) {
        f0 = *(const float4*)(ap + 0);  f1 = *(const float4*)(ap + 4);
        f2 = *(const float4*)(ap + 8);  f3 = *(const float4*)(ap + 12);
    } else {
        f0 = *(const float4*)(bp0);     f1 = *(const float4*)(bp0 + 4);
        f2 = *(const float4*)(bp1);     f3 = *(const float4*)(bp1 + 4);
    }

    const int NIT = LM / 16;    // 16
    for (int it = 0; it < NIT; it++) {
        int buf = it & 1;
        if (isA) {
            uint32_t* R = &As[buf][alr][0];
            R[0] = h2pack(f0.x, f0.y); R[2] = h2pack(f0.z, f0.w);
            R[4] = h2pack(f1.x, f1.y); R[6] = h2pack(f1.z, f1.w);
            R[1] = h2pack(f2.x, f2.y); R[3] = h2pack(f2.z, f2.w);
            R[5] = h2pack(f3.x, f3.y); R[7] = h2pack(f3.z, f3.w);
        } else {
            uint32_t* R = &Bs[buf][bkp][bc0];
            R[0] = h2pack(f0.x, f2.x); R[1] = h2pack(f0.y, f2.y);
            R[2] = h2pack(f0.z, f2.z); R[3] = h2pack(f0.w, f2.w);
            R[4] = h2pack(f1.x, f3.x); R[5] = h2pack(f1.y, f3.y);
            R[6] = h2pack(f1.z, f3.z); R[7] = h2pack(f1.w, f3.w);
        }
        __syncthreads();
        if (it + 1 < NIT) {
            int k0 = (it + 1) * 16;
            if (isA) {
                f0 = *(const float4*)(ap + k0 + 0);  f1 = *(const float4*)(ap + k0 + 4);
                f2 = *(const float4*)(ap + k0 + 8);  f3 = *(const float4*)(ap + k0 + 12);
            } else {
                f0 = *(const float4*)(bp0 + k0 * LM);      f1 = *(const float4*)(bp0 + k0 * LM + 4);
                f2 = *(const float4*)(bp1 + k0 * LM);      f3 = *(const float4*)(bp1 + k0 * LM + 4);
            }
        }
        uint2 A0[2], A1[2];
        #pragma unroll
        for (int mt = 0; mt < 2; mt++) {
            int rr = wm * 32 + mt * 16 + g;
            A0[mt] = *(uint2*)&As[buf][rr][tig * 2];
            A1[mt] = *(uint2*)&As[buf][rr + 8][tig * 2];
        }
        #pragma unroll
        for (int nt = 0; nt < 4; nt++) {
            int nn = wn * 32 + nt * 8 + g;
            uint32_t b0 = Bs[buf][tig][nn];
            uint32_t b1 = Bs[buf][tig + 4][nn];
            #pragma unroll
            for (int mt = 0; mt < 2; mt++)
                mma_f16(acc[mt][nt][0], acc[mt][nt][1], acc[mt][nt][2], acc[mt][nt][3],
                        A0[mt].x, A1[mt].x, A0[mt].y, A1[mt].y, b0, b1);
        }
        __syncthreads();
    }

    #pragma unroll
    for (int mt = 0; mt < 2; mt++) {
        int r1 = row0 + wm * 32 + mt * 16 + g;
        int r2 = r1 + 8;
        #pragma unroll
        for (int nt = 0; nt < 4; nt++) {
            int cc = col0 + wn * 32 + nt * 8 + tig * 2;
            long i1 = (long)r1 * LM + cc, i2 = (long)r2 * LM + cc;
            float v0 = c0 * acc[mt][nt][0], v1 = c0 * acc[mt][nt][1];
            float v2 = c0 * acc[mt][nt][2], v3 = c0 * acc[mt][nt][3];
            if (c1 != 0.f) {
                v0 += c1 * Xp[i1]; v1 += c1 * Xp[i1 + 1];
                v2 += c1 * Xp[i2]; v3 += c1 * Xp[i2 + 1];
            }
            C[i1] = v0; C[i1 + 1] = v1; C[i2] = v2; C[i2 + 1] = v3;
        }
    }
}

// -------------------- fp32 batched 256^3 GEMM (final pinv iter) -------------
__global__ void __launch_bounds__(256) sgemm64_kernel(
    const float* __restrict__ A, const float* __restrict__ B,
    float* __restrict__ C, const float* __restrict__ X,
    float c0, float c1)
{
    long off = (long)blockIdx.z * (LM*LM);
    A += off; B += off; C += off;
    const float* Xp = X ? X + off : (const float*)0;
    __shared__ float As[2][16][64];
    __shared__ float Bs[2][16][64];
    int row0 = blockIdx.x * 64, col0 = blockIdx.y * 64;
    int tid = threadIdx.x;
    int tx = tid & 15, ty = tid >> 4;
    int ar = tid >> 2, ac = (tid & 3) * 4;
    int br = tid >> 4, bc = (tid & 15) * 4;

    const float* Aptr = A + (row0 + ar) * LM + ac;
    const float* Bptr = B + br * LM + col0 + bc;

    float acc[4][4];
    #pragma unroll
    for (int i=0;i<4;i++)
        #pragma unroll
        for (int j=0;j<4;j++) acc[i][j]=0.f;

    float4 a4 = *(const float4*)(Aptr);
    float4 b4 = *(const float4*)(Bptr);
    As[0][ac+0][ar]=a4.x; As[0][ac+1][ar]=a4.y; As[0][ac+2][ar]=a4.z; As[0][ac+3][ar]=a4.w;
    *(float4*)&Bs[0][br][bc] = b4;
    __syncthreads();

    const int nk = LM / 16;
    for (int t = 0; t < nk; t++) {
        int buf = t & 1;
        float4 na, nb;
        if (t + 1 < nk) {
            int k0 = (t + 1) * 16;
            na = *(const float4*)(Aptr + k0);
            nb = *(const float4*)(Bptr + k0 * LM);
        }
        #pragma unroll
        for (int kk=0; kk<16; kk++) {
            float a0[4], b0[4];
            *(float4*)&a0[0] = *(float4*)&As[buf][kk][ty*4];
            *(float4*)&b0[0] = *(float4*)&Bs[buf][kk][tx*4];
            #pragma unroll
            for (int i=0;i<4;i++)
                #pragma unroll
                for (int j=0;j<4;j++) acc[i][j] += a0[i]*b0[j];
        }
        if (t + 1 < nk) {
            int nb_ = buf ^ 1;
            As[nb_][ac+0][ar]=na.x; As[nb_][ac+1][ar]=na.y;
            As[nb_][ac+2][ar]=na.z; As[nb_][ac+3][ar]=na.w;
            *(float4*)&Bs[nb_][br][bc] = nb;
            __syncthreads();
        }
    }
    #pragma unroll
    for (int i=0;i<4;i++) {
        int r = row0 + ty*4 + i;
        #pragma unroll
        for (int j=0;j<4;j++) {
            int c = col0 + tx*4 + j;
            long idx = (long)r * LM + c;
            float v = c0 * acc[i][j];
            if (c1 != 0.f) v += c1 * Xp[idx];
            C[idx] = v;
        }
    }
}

// ------------------------------ helpers ------------------------------------
static __device__ __forceinline__ float blockSum128(float v) {
    __shared__ float sh[4];
    #pragma unroll
    for (int o = 16; o; o >>= 1) v += __shfl_xor_sync(0xffffffffu, v, o);
    __syncthreads();
    if ((threadIdx.x & 31) == 0) sh[threadIdx.x >> 5] = v;
    __syncthreads();
    return sh[0] + sh[1] + sh[2] + sh[3];
}

// ------------------------------ layernorm -----------------------------------
__global__ void ln_pad_kernel(const float* __restrict__ in, float* __restrict__ out,
                              const float* __restrict__ g, const float* __restrict__ b)
{
    int p = blockIdx.x;
    int tid = threadIdx.x;
    float* orow = out + (long)p * HID;
    if (p < PADR) {
        *(float4*)(orow + tid*4) = make_float4(0.f,0.f,0.f,0.f);
        return;
    }
    const float* x = in + (long)(p - PADR) * HID;
    float4 v = *(const float4*)(x + tid*4);
    float s = blockSum128(v.x+v.y+v.z+v.w);
    float mu = s * (1.f/512.f);
    float d0=v.x-mu, d1=v.y-mu, d2=v.z-mu, d3=v.w-mu;
    float sq = blockSum128(d0*d0+d1*d1+d2*d2+d3*d3);
    float rstd = rsqrtf(sq*(1.f/512.f) + 1e-5f);
    int c = tid*4;
    orow[c+0]=d0*rstd*g[c+0]+b[c+0]; orow[c+1]=d1*rstd*g[c+1]+b[c+1];
    orow[c+2]=d2*rstd*g[c+2]+b[c+2]; orow[c+3]=d3*rstd*g[c+3]+b[c+3];
}

__global__ void final_ln_kernel(const float* __restrict__ in,
                                const float* __restrict__ g, const float* __restrict__ b,
                                float* __restrict__ out)
{
    int tid = threadIdx.x;
    float4 v = *(const float4*)(in + tid*4);
    float s = blockSum128(v.x+v.y+v.z+v.w);
    float mu = s * (1.f/512.f);
    float d0=v.x-mu, d1=v.y-mu, d2=v.z-mu, d3=v.w-mu;
    float sq = blockSum128(d0*d0+d1*d1+d2*d2+d3*d3);
    float rstd = rsqrtf(sq*(1.f/512.f) + 1e-5f);
    int c = tid*4;
    out[c+0]=d0*rstd*g[c+0]+b[c+0]; out[c+1]=d1*rstd*g[c+1]+b[c+1];
    out[c+2]=d2*rstd*g[c+2]+b[c+2]; out[c+3]=d3*rstd*g[c+3]+b[c+3];
}

// ------------------------------ landmarks -----------------------------------
__global__ void landmark_kernel()
{
    int i = blockIdx.x;
    int c = threadIdx.x;
    const float* base = g_qkv + (long)i * LSEG * QKV3 + c;
    float s = 0.f;
    #pragma unroll 7
    for (int t = 0; t < LSEG; t++) s += base[(long)t * QKV3];
    s *= (1.f/77.f);
    if (c < 64) g_ql[((c>>3)*LM + i)*DH + (c&7)] = s;
    else { int c2 = c-64; g_kl[((c2>>3)*LM + i)*DH + (c2&7)] = s; }
}

// --------------------------- attn2 + softmax --------------------------------
__global__ void attn2_kernel()
{
    int i = blockIdx.x, h = blockIdx.y;
    int j = threadIdx.x;
    __shared__ float red[256];
    const float* qi = g_ql + (h*LM + i)*DH;
    const float* kj = g_kl + (h*LM + j)*DH;
    float dot = 0.f;
    #pragma unroll
    for (int d = 0; d < DH; d++) dot += qi[d]*kj[d];
    red[j] = dot; __syncthreads();
    for (int s = 128; s > 0; s >>= 1) { if (j < s) red[j] = fmaxf(red[j], red[j+s]); __syncthreads(); }
    float m = red[0]; __syncthreads();
    float p = expf(dot - m);
    red[j] = p; __syncthreads();
    for (int s = 128; s > 0; s >>= 1) { if (j < s) red[j] += red[j+s]; __syncthreads(); }
    g_a2[(h*LM + i)*LM + j] = p / red[0];
}

__global__ void zero_scale_kernel() { g_scale_bits = 0u; }

__global__ void colmax_kernel()
{
    int h = blockIdx.x, j = threadIdx.x;
    __shared__ float red[256];
    const float* col = g_a2 + h*(LM*LM) + j;
    float s = 0.f;
    for (int i = 0; i < LM; i++) s += col[i*LM];
    red[j] = s; __syncthreads();
    for (int k = 128; k > 0; k >>= 1) { if (j < k) red[j] = fmaxf(red[j], red[j+k]); __syncthreads(); }
    if (j == 0) atomicMax(&g_scale_bits, __float_as_uint(red[0]));
}

__global__ void zinit_kernel()
{
    int i = blockIdx.x, h = blockIdx.y, j = threadIdx.x;
    float scale = __uint_as_float(g_scale_bits);
    g_z0[h*(LM*LM) + i*LM + j] = g_a2[h*(LM*LM) + j*LM + i] / scale;
}

// --------------- attn3 @ v (single pass, no max subtraction) ----------------
__global__ void __launch_bounds__(256) attn3_kernel()
{
    int h = blockIdx.y;
    int tid = threadIdx.x;
    int lmi = tid >> 3, sub = tid & 7;
    int L0 = blockIdx.x * 32 + lmi;
    __shared__ float kt[256][9];
    __shared__ float vt[256][9];

    float q[8];
    #pragma unroll
    for (int d = 0; d < 8; d++) q[d] = g_ql[(h*LM + L0)*DH + d];

    float s = 0.f, acc[8];
    #pragma unroll
    for (int d = 0; d < 8; d++) acc[d] = 0.f;
    for (int t0 = 0; t0 < NP; t0 += 256) {
        const float* kr = g_qkv + (long)(t0 + tid) * QKV3 + 64 + h*8;
        #pragma unroll
        for (int d = 0; d < 8; d++) { kt[tid][d] = kr[d]; vt[tid][d] = kr[64+d]; }
        __syncthreads();
        for (int j = sub; j < 256; j += 8) {
            float dot = 0.f;
            #pragma unroll
            for (int d = 0; d < 8; d++) dot += q[d]*kt[j][d];
            float p = expf(dot);           // scores bounded; softmax shift-invariant
            s += p;
            #pragma unroll
            for (int d = 0; d < 8; d++) acc[d] += p * vt[j][d];
        }
        __syncthreads();
    }
    #pragma unroll
    for (int o = 4; o; o >>= 1) {
        s += __shfl_xor_sync(0xffffffffu, s, o);
        #pragma unroll
        for (int d = 0; d < 8; d++) acc[d] += __shfl_xor_sync(0xffffffffu, acc[d], o);
    }
    if (sub == 0) {
        float inv = 1.f / s;
        #pragma unroll
        for (int d = 0; d < 8; d++) g_av[(h*LM + L0)*DH + d] = acc[d]*inv;
    }
}

// --------------------------- W = pinv(a2) @ av ------------------------------
__global__ void wmat_kernel()
{
    int h = blockIdx.x, r = threadIdx.x;
    __shared__ float avs[256][8];
    #pragma unroll
    for (int d = 0; d < 8; d++) avs[r][d] = g_av[(h*LM + r)*DH + d];
    __syncthreads();
    const float* zr = g_z0 + h*(LM*LM) + r*LM;
    float acc[8];
    #pragma unroll
    for (int d = 0; d < 8; d++) acc[d] = 0.f;
    for (int k = 0; k < LM; k++) {
        float zv = zr[k];
        #pragma unroll
        for (int d = 0; d < 8; d++) acc[d] += zv * avs[k][d];
    }
    #pragma unroll
    for (int d = 0; d < 8; d++) g_W[(h*LM + r)*DH + d] = acc[d];
}

// ---------- attn1 @ W + dwconv(v) (no max subtraction) ----------------------
__global__ void __launch_bounds__(256) attn1_kernel(const float* __restrict__ resw)
{
    int h = blockIdx.y;
    int tid = threadIdx.x;
    int i = blockIdx.x * 256 + tid;
    __shared__ float kl[256][8];
    __shared__ float Wm[256][8];
    __shared__ float cw[33];
    {
        const float* ks = g_kl + (h*LM + tid)*DH;
        const float* ws = g_W  + (h*LM + tid)*DH;
        *(float4*)&kl[tid][0] = *(const float4*)(ks);
        *(float4*)&kl[tid][4] = *(const float4*)(ks+4);
        *(float4*)&Wm[tid][0] = *(const float4*)(ws);
        *(float4*)&Wm[tid][4] = *(const float4*)(ws+4);
        if (tid < 33) cw[tid] = resw[h*33 + tid];
    }
    __syncthreads();
    if (i >= NSEQ) return;
    int t = PADR + i;
    float q[8];
    {
        const float* qr = g_qkv + (long)t * QKV3 + h*8;
        #pragma unroll
        for (int d = 0; d < 8; d++) q[d] = qr[d];
    }
    float s = 0.f, acc[8];
    #pragma unroll
    for (int d = 0; d < 8; d++) acc[d] = 0.f;
    for (int j = 0; j < 256; j++) {
        float4 k0 = *(float4*)&kl[j][0];
        float4 k1 = *(float4*)&kl[j][4];
        float dot = q[0]*k0.x + q[1]*k0.y + q[2]*k0.z + q[3]*k0.w
                  + q[4]*k1.x + q[5]*k1.y + q[6]*k1.z + q[7]*k1.w;
        float p = expf(dot);               // scores bounded; softmax shift-invariant
        s += p;
        float4 w0 = *(float4*)&Wm[j][0];
        float4 w1 = *(float4*)&Wm[j][4];
        acc[0]+=p*w0.x; acc[1]+=p*w0.y; acc[2]+=p*w0.z; acc[3]+=p*w0.w;
        acc[4]+=p*w1.x; acc[5]+=p*w1.y; acc[6]+=p*w1.z; acc[7]+=p*w1.w;
    }
    float inv = 1.f / s;
    float o[8];
    #pragma unroll
    for (int d = 0; d < 8; d++) o[d] = acc[d]*inv;
    #pragma unroll 4
    for (int k = 0; k < 33; k++) {
        int r = t + k - 16;
        if (r < NP) {
            const float* vr = g_qkv + (long)r * QKV3 + 128 + h*8;
            float4 v0 = *(const float4*)(vr);
            float4 v1 = *(const float4*)(vr+4);
            float c = cw[k];
            o[0]+=c*v0.x; o[1]+=c*v0.y; o[2]+=c*v0.z; o[3]+=c*v0.w;
            o[4]+=c*v1.x; o[5]+=c*v1.y; o[6]+=c*v1.z; o[7]+=c*v1.w;
        }
    }
    float* outp = g_attnout + (long)i * INNER + h*8;
    *(float4*)(outp)   = make_float4(o[0],o[1],o[2],o[3]);
    *(float4*)(outp+4) = make_float4(o[4],o[5],o[6],o[7]);
}

// ------------------------------ PPEG ----------------------------------------
__global__ void ppeg_prep(const float* __restrict__ w7, const float* __restrict__ b7,
                          const float* __restrict__ w5, const float* __restrict__ b5,
                          const float* __restrict__ w3, const float* __restrict__ b3)
{
    int c = blockIdx.x;
    int k = threadIdx.x;
    if (k < 49) {
        int dy = k/7 - 3, dx = k%7 - 3;
        float w = w7[c*49 + k];
        if (dy >= -2 && dy <= 2 && dx >= -2 && dx <= 2) w += w5[c*25 + (dy+2)*5 + (dx+2)];
        if (dy >= -1 && dy <= 1 && dx >= -1 && dx <= 1) w += w3[c*9 + (dy+1)*3 + (dx+1)];
        if (dy == 0 && dx == 0) w += 1.f;
        g_wcomb[k*HID + c] = w;
    }
    if (k == 0) g_bcomb[c] = b7[c] + b5[c] + b3[c];
}

__global__ void __launch_bounds__(256) ppeg_kernel()
{
    int cg = blockIdx.z;
    int px0 = blockIdx.x*8, py0 = blockIdx.y*8;
    int tid = threadIdx.x;
    int cl = tid & 31, pidx = tid >> 5;
    __shared__ float insh[14][14][32];
    __shared__ float wsh[49][32];
    __shared__ float bsh[32];
    for (int idx = tid; idx < 14*14*32; idx += 256) {
        int ch = idx & 31; int pos = idx >> 5;
        int iy = pos/14, ix = pos%14;
        int gy = py0 + iy - 3, gx = px0 + ix - 3;
        float v = 0.f;
        if (gy >= 0 && gy < 140 && gx >= 0 && gx < 140)
            v = g_h[(long)(1 + gy*140 + gx)*HID + cg*32 + ch];
        insh[iy][ix][ch] = v;
    }
    for (int idx = tid; idx < 49*32; idx += 256) {
        int ch = idx & 31, k = idx >> 5;
        wsh[k][ch] = g_wcomb[k*HID + cg*32 + ch];
    }
    if (tid < 32) bsh[tid] = g_bcomb[cg*32 + tid];
    __syncthreads();

    int c = cg*32 + cl;
    int gx = px0 + pidx;
    if (gx >= 140) return;
    for (int yy = 0; yy < 8; yy++) {
        int gy = py0 + yy;
        if (gy >= 140) break;
        float acc = bsh[cl];
        #pragma unroll
        for (int dy = 0; dy < 7; dy++)
            #pragma unroll
            for (int dx = 0; dx < 7; dx++)
                acc += wsh[dy*7+dx][cl] * insh[yy+dy][pidx+dx][cl];
        g_hb[(long)(1 + gy*140 + gx)*HID + c] = acc;
    }
}

__global__ void copy_cls(const float* __restrict__ src, float* __restrict__ dst)
{
    int t = threadIdx.x;
    dst[t] = src[t];
    dst[t+256] = src[t+256];
}

// ------------------------------ host orchestration --------------------------
extern "C" void kernel_launch(void* const* d_in, const int* in_sizes, int n_in,
                              void* d_out, int out_size)
{
    (void)in_sizes; (void)n_in; (void)out_size;
    const float* x       = (const float*)d_in[0];
    const float* fc1_w   = (const float*)d_in[1];
    const float* fc1_b   = (const float*)d_in[2];
    const float* cls_tok = (const float*)d_in[3];
    const float* l_ng[2] = {(const float*)d_in[4],  (const float*)d_in[10]};
    const float* l_nb[2] = {(const float*)d_in[5],  (const float*)d_in[11]};
    const float* l_qw[2] = {(const float*)d_in[6],  (const float*)d_in[12]};
    const float* l_ow[2] = {(const float*)d_in[7],  (const float*)d_in[13]};
    const float* l_ob[2] = {(const float*)d_in[8],  (const float*)d_in[14]};
    const float* l_rw[2] = {(const float*)d_in[9],  (const float*)d_in[15]};
    const float* p7w = (const float*)d_in[16];
    const float* p7b = (const float*)d_in[17];
    const float* p5w = (const float*)d_in[18];
    const float* p5b = (const float*)d_in[19];
    const float* p3w = (const float*)d_in[20];
    const float* p3b = (const float*)d_in[21];
    const float* norm_g = (const float*)d_in[22];
    const float* norm_b = (const float*)d_in[23];

    float *h, *hb, *xpad, *qkv, *attnout, *a2, *z0, *z1, *az, *t1, *t2;
    float *wT, *qkvT, *owT;
    cudaGetSymbolAddress((void**)&h,  g_h);
    cudaGetSymbolAddress((void**)&hb, g_hb);
    cudaGetSymbolAddress((void**)&xpad, g_xpad);
    cudaGetSymbolAddress((void**)&qkv,  g_qkv);
    cudaGetSymbolAddress((void**)&attnout, g_attnout);
    cudaGetSymbolAddress((void**)&a2, g_a2);
    cudaGetSymbolAddress((void**)&z0, g_z0);
    cudaGetSymbolAddress((void**)&z1, g_z1);
    cudaGetSymbolAddress((void**)&az, g_az);
    cudaGetSymbolAddress((void**)&t1, g_t1m);
    cudaGetSymbolAddress((void**)&t2, g_t2m);
    cudaGetSymbolAddress((void**)&wT, g_wT);
    cudaGetSymbolAddress((void**)&qkvT, g_qkvT);
    cudaGetSymbolAddress((void**)&owT, g_owT);

    // fc1 + GELU via mma.sync fp16 -> rows 1.. of g_h; cls -> row 0
    transpose_pad_kernel<<<dim3(IND/32, HID/32), dim3(32,8)>>>(fc1_w, wT, IND, HID);
    gemm_mma_kernel<1><<<dim3(154, 4), 256>>>(x, wT, h + HID, fc1_b,
                                              NTOK, HID, IND, IND, HID);
    copy_cls<<<1,256>>>(cls_tok, h);

    for (int layer = 0; layer < 2; layer++) {
        float* hcur = (layer == 0) ? h : hb;

        ln_pad_kernel<<<NP,128>>>(hcur, xpad, l_ng[layer], l_nb[layer]);
        transpose_pad_kernel<<<dim3(HID/32, 256/32), dim3(32,8)>>>(l_qw[layer], qkvT, HID, QKV3);
        gemm_mma_kernel<2><<<dim3(154, 2), 256>>>(xpad, qkvT, qkv, (const float*)0,
                                                  NP, QKV3, HID, HID, QKV3);
        landmark_kernel<<<LM,128>>>();
        attn2_kernel<<<dim3(LM,HEADS),256>>>();
        zero_scale_kernel<<<1,1>>>();
        colmax_kernel<<<HEADS,256>>>();
        zinit_kernel<<<dim3(LM,HEADS),256>>>();
        attn3_kernel<<<dim3(8,HEADS),256>>>();

        for (int it = 0; it < 6; it++) {
            float* zin  = (it & 1) ? z1 : z0;
            float* zout = (it & 1) ? z0 : z1;
            dim3 gp(4,4,HEADS);
            if (it < 5) {
                pinv_mma_kernel<<<gp,128>>>(a2, zin, az, (const float*)0, 1.f, 0.f);
                pinv_mma_kernel<<<gp,128>>>(az, az, t1, az, -1.f, 7.f);
                pinv_mma_kernel<<<gp,128>>>(az, t1, t2, az, -1.f, 15.f);
                pinv_mma_kernel<<<gp,128>>>(zin, t2, zout, zin, -0.25f, 3.25f);
            } else {   // final iteration in fp32 (Newton self-correction)
                sgemm64_kernel<<<gp,256>>>(a2, zin, az, (const float*)0, 1.f, 0.f);
                sgemm64_kernel<<<gp,256>>>(az, az, t1, az, -1.f, 7.f);
                sgemm64_kernel<<<gp,256>>>(az, t1, t2, az, -1.f, 15.f);
                sgemm64_kernel<<<gp,256>>>(zin, t2, zout, zin, -0.25f, 3.25f);
            }
        }
        wmat_kernel<<<HEADS,256>>>();
        attn1_kernel<<<dim3(77,HEADS),256>>>(l_rw[layer]);
        transpose_pad_kernel<<<dim3(INNER/32, HID/32), dim3(32,8)>>>(l_ow[layer], owT, INNER, HID);
        gemm_mma_kernel<3><<<dim3(154, 4), 256>>>(attnout, owT, hcur, l_ob[layer],
                                                  NSEQ, HID, INNER, INNER, HID);
        if (layer == 0) {
            ppeg_prep<<<HID,64>>>(p7w, p7b, p5w, p5b, p3w, p3b);
            ppeg_kernel<<<dim3(18,18,16),256>>>();
            copy_cls<<<1,256>>>(h, hb);
        }
    }
    final_ln_kernel<<<1,128>>>(hb, norm_g, norm_b, (float*)d_out);
}